// round 3
// baseline (speedup 1.0000x reference)
#include <cuda_runtime.h>
#include <math_constants.h>
#include <cstdint>

#define BB 4
#define TT 2048
#define CC 1024
#define HH 128

// scratch: q,k,v projections [B,T,H]
__device__ float g_q[BB * TT * HH];
__device__ float g_k[BB * TT * HH];
__device__ float g_v[BB * TT * HH];

// attention partials: [B][32 qtiles][4 chunks]
__device__ float g_po[BB * 32 * 4 * 64 * HH];
__device__ float g_pm[BB * 32 * 4 * 64];
__device__ float g_pl[BB * 32 * 4 * 64];

// ---------------------------------------------------------------------------
// tf32 helpers
// ---------------------------------------------------------------------------
__device__ __forceinline__ uint32_t f2tf(float x) {
    uint32_t r;
    asm("cvt.rna.tf32.f32 %0, %1;" : "=r"(r) : "f"(x));
    return r;
}

__device__ __forceinline__ void mma_tf32(float c[4],
                                         uint32_t a0, uint32_t a1,
                                         uint32_t a2, uint32_t a3,
                                         uint32_t b0, uint32_t b1) {
    asm volatile(
        "mma.sync.aligned.m16n8k8.row.col.f32.tf32.tf32.f32 "
        "{%0,%1,%2,%3}, {%4,%5,%6,%7}, {%8,%9}, {%0,%1,%2,%3};"
        : "+f"(c[0]), "+f"(c[1]), "+f"(c[2]), "+f"(c[3])
        : "r"(a0), "r"(a1), "r"(a2), "r"(a3), "r"(b0), "r"(b1));
}

// ---------------------------------------------------------------------------
// Projection GEMM via tf32 mma.sync, 3xTF32 split (hi*hi + hi*lo + lo*hi).
// out[m,h] = sum_c x[m,c] * W[c,h].  M=8192, K=1024, N=128.
// Block: 64 (M) x 128 (N), BK=32, 256 threads = 8 warps (2 Mwarps x 4 Nwarps),
// each warp 32x32, = 2x4 m16n8k8 tiles.
// Smem strides chosen for conflict-free fragment loads:
//   X stride 36 (36 mod 32 == 4 -> bank = 4*g + tg, all distinct)
//   W stride 136 (136 mod 32 == 8 -> bank = 8*tg + g, all distinct)
// ---------------------------------------------------------------------------
#define XS 36
#define WS 136
#define PROJ_SMEM_U32 (2 * 64 * XS + 2 * 32 * WS)   // 13312 u32 = 53248 B

__global__ __launch_bounds__(256) void proj_kernel(
    const float* __restrict__ x,
    const float* __restrict__ Wq,
    const float* __restrict__ Wk,
    const float* __restrict__ Wv)
{
    extern __shared__ uint32_t psm[];
    uint32_t* Xh = psm;                 // 64*XS
    uint32_t* Xl = Xh + 64 * XS;
    uint32_t* Wh = Xl + 64 * XS;        // 32*WS
    uint32_t* Wl = Wh + 32 * WS;

    const float* W;
    float* dst;
    if (blockIdx.y == 0)      { W = Wq; dst = g_q; }
    else if (blockIdx.y == 1) { W = Wk; dst = g_k; }
    else                      { W = Wv; dst = g_v; }

    const int tid  = threadIdx.x;
    const int lane = tid & 31;
    const int wid  = tid >> 5;
    const int wm   = wid & 1;        // warp row (2)
    const int wn   = wid >> 1;       // warp col (4)
    const int g    = lane >> 2;      // group id 0..7
    const int tg   = lane & 3;       // thread in group 0..3
    const int m0   = blockIdx.x * 64;

    // loader indices
    const int xrow = tid >> 2;           // 0..63
    const int xkq  = (tid & 3) * 8;      // 0,8,16,24
    const int wrow = tid >> 3;           // 0..31
    const int wcb  = (tid & 7) * 16;     // 0..112

    float acc[2][4][4];
#pragma unroll
    for (int mt = 0; mt < 2; mt++)
#pragma unroll
        for (int nt = 0; nt < 4; nt++)
#pragma unroll
            for (int i = 0; i < 4; i++) acc[mt][nt][i] = 0.f;

    for (int k0 = 0; k0 < CC; k0 += 32) {
        __syncthreads();
        // X tile 64x32 -> hi/lo
#pragma unroll
        for (int u = 0; u < 2; u++) {
            float4 xv = *(const float4*)(x + (size_t)(m0 + xrow) * CC + k0 + xkq + 4 * u);
            const float vv[4] = {xv.x, xv.y, xv.z, xv.w};
#pragma unroll
            for (int j = 0; j < 4; j++) {
                uint32_t h = f2tf(vv[j]);
                float lo = vv[j] - __uint_as_float(h);
                Xh[xrow * XS + xkq + 4 * u + j] = h;
                Xl[xrow * XS + xkq + 4 * u + j] = f2tf(lo);
            }
        }
        // W tile 32x128 -> hi/lo
#pragma unroll
        for (int u = 0; u < 4; u++) {
            float4 wv = *(const float4*)(W + (size_t)(k0 + wrow) * HH + wcb + 4 * u);
            const float vv[4] = {wv.x, wv.y, wv.z, wv.w};
#pragma unroll
            for (int j = 0; j < 4; j++) {
                uint32_t h = f2tf(vv[j]);
                float lo = vv[j] - __uint_as_float(h);
                Wh[wrow * WS + wcb + 4 * u + j] = h;
                Wl[wrow * WS + wcb + 4 * u + j] = f2tf(lo);
            }
        }
        __syncthreads();

#pragma unroll
        for (int ks = 0; ks < 4; ks++) {
            const int kb = ks * 8;
            uint32_t ah[2][4], al[2][4];
#pragma unroll
            for (int mt = 0; mt < 2; mt++) {
                const int r0 = wm * 32 + mt * 16;
                ah[mt][0] = Xh[(r0 + g)     * XS + kb + tg];
                ah[mt][1] = Xh[(r0 + g + 8) * XS + kb + tg];
                ah[mt][2] = Xh[(r0 + g)     * XS + kb + tg + 4];
                ah[mt][3] = Xh[(r0 + g + 8) * XS + kb + tg + 4];
                al[mt][0] = Xl[(r0 + g)     * XS + kb + tg];
                al[mt][1] = Xl[(r0 + g + 8) * XS + kb + tg];
                al[mt][2] = Xl[(r0 + g)     * XS + kb + tg + 4];
                al[mt][3] = Xl[(r0 + g + 8) * XS + kb + tg + 4];
            }
            uint32_t bh[4][2], bl[4][2];
#pragma unroll
            for (int nt = 0; nt < 4; nt++) {
                const int c0 = wn * 32 + nt * 8 + g;
                bh[nt][0] = Wh[(kb + tg)     * WS + c0];
                bh[nt][1] = Wh[(kb + tg + 4) * WS + c0];
                bl[nt][0] = Wl[(kb + tg)     * WS + c0];
                bl[nt][1] = Wl[(kb + tg + 4) * WS + c0];
            }
#pragma unroll
            for (int mt = 0; mt < 2; mt++)
#pragma unroll
                for (int nt = 0; nt < 4; nt++) {
                    mma_tf32(acc[mt][nt], ah[mt][0], ah[mt][1], ah[mt][2], ah[mt][3],
                             bh[nt][0], bh[nt][1]);
                    mma_tf32(acc[mt][nt], ah[mt][0], ah[mt][1], ah[mt][2], ah[mt][3],
                             bl[nt][0], bl[nt][1]);
                    mma_tf32(acc[mt][nt], al[mt][0], al[mt][1], al[mt][2], al[mt][3],
                             bh[nt][0], bh[nt][1]);
                }
        }
    }

    // epilogue
#pragma unroll
    for (int mt = 0; mt < 2; mt++) {
        const int rbase = m0 + wm * 32 + mt * 16;
#pragma unroll
        for (int nt = 0; nt < 4; nt++) {
            const int col = wn * 32 + nt * 8 + 2 * tg;
            *(float2*)(dst + (size_t)(rbase + g) * HH + col) =
                make_float2(acc[mt][nt][0], acc[mt][nt][1]);
            *(float2*)(dst + (size_t)(rbase + g + 8) * HH + col) =
                make_float2(acc[mt][nt][2], acc[mt][nt][3]);
        }
    }
}

// ---------------------------------------------------------------------------
// Flash attention, split-KV balanced: block = (qtile, batch, chunk).
// chunk c covers key tiles [8c, min(8c+8, qt+1)); invalid chunks exit.
// Writes unnormalized partial O + (m, l); combine kernel merges.
// ---------------------------------------------------------------------------
#define ATT_SMEM_FLOATS (64 * 132 * 2 + 64 * 65)

__global__ __launch_bounds__(256, 2) void attn_kernel()
{
    const int qt = blockIdx.x;       // 0..31
    const int b  = blockIdx.y;       // 0..3
    const int ch = blockIdx.z;       // 0..3
    if (ch * 8 > qt) return;         // invalid chunk

    extern __shared__ float sm[];
    float* Qs  = sm;                 // 64*132
    float* KVs = sm + 64 * 132;      // 64*132
    float* Ss  = sm + 2 * 64 * 132;  // 64*65

    __shared__ float m_sh[64];
    __shared__ float l_sh[64];
    __shared__ float f_sh[64];
    __shared__ float red[64 * 4];

    const int tid = threadIdx.x;
    const int tx = tid & 15;
    const int ty = tid >> 4;

    const float* qp = g_q + (size_t)b * TT * HH;
    const float* kp = g_k + (size_t)b * TT * HH;
    const float* vp = g_v + (size_t)b * TT * HH;

    const int lr  = tid >> 2;
    const int lc0 = (tid & 3) * 32;
    const int r0  = qt * 64;

    // load Q tile
#pragma unroll
    for (int u = 0; u < 8; u++) {
        const int c = lc0 + 4 * u;
        *(float4*)(Qs + lr * 132 + c) =
            *(const float4*)(qp + (size_t)(r0 + lr) * HH + c);
    }
    if (tid < 64) { m_sh[tid] = -CUDART_INF_F; l_sh[tid] = 0.f; }

    float acc[4][8];
#pragma unroll
    for (int r = 0; r < 4; r++)
#pragma unroll
        for (int i = 0; i < 8; i++) acc[r][i] = 0.f;

    const float inv_scale = 0.03125f;  // C^-0.5 = 1/32

    const int jt0 = ch * 8;
    const int jt1 = min(jt0 + 8, qt + 1);

    for (int jt = jt0; jt < jt1; jt++) {
        const int j0 = jt * 64;
        __syncthreads();
#pragma unroll
        for (int u = 0; u < 8; u++) {
            const int c = lc0 + 4 * u;
            *(float4*)(KVs + lr * 132 + c) =
                *(const float4*)(kp + (size_t)(j0 + lr) * HH + c);
        }
        __syncthreads();

        // S = Q K^T
        float s[4][4];
#pragma unroll
        for (int r = 0; r < 4; r++)
#pragma unroll
            for (int c2 = 0; c2 < 4; c2++) s[r][c2] = 0.f;

#pragma unroll 4
        for (int h = 0; h < HH; h += 4) {
            float4 q4[4], k4[4];
#pragma unroll
            for (int r = 0; r < 4; r++)
                q4[r] = *(const float4*)(Qs + (ty + 16 * r) * 132 + h);
#pragma unroll
            for (int c2 = 0; c2 < 4; c2++)
                k4[c2] = *(const float4*)(KVs + (tx + 16 * c2) * 132 + h);
#pragma unroll
            for (int r = 0; r < 4; r++)
#pragma unroll
                for (int c2 = 0; c2 < 4; c2++) {
                    s[r][c2] = fmaf(q4[r].x, k4[c2].x, s[r][c2]);
                    s[r][c2] = fmaf(q4[r].y, k4[c2].y, s[r][c2]);
                    s[r][c2] = fmaf(q4[r].z, k4[c2].z, s[r][c2]);
                    s[r][c2] = fmaf(q4[r].w, k4[c2].w, s[r][c2]);
                }
        }

        // scale (+ mask only on the diagonal tile), store to Ss
        if (jt == qt) {
#pragma unroll
            for (int r = 0; r < 4; r++) {
                const int rg = r0 + ty + 16 * r;
#pragma unroll
                for (int c2 = 0; c2 < 4; c2++) {
                    const int jg = j0 + tx + 16 * c2;
                    float v = s[r][c2] * inv_scale;
                    if (jg > rg) v = -CUDART_INF_F;
                    Ss[(ty + 16 * r) * 65 + tx + 16 * c2] = v;
                }
            }
        } else {
#pragma unroll
            for (int r = 0; r < 4; r++)
#pragma unroll
                for (int c2 = 0; c2 < 4; c2++)
                    Ss[(ty + 16 * r) * 65 + tx + 16 * c2] = s[r][c2] * inv_scale;
        }
        __syncthreads();

        // prefetch V (overlaps softmax)
#pragma unroll
        for (int u = 0; u < 8; u++) {
            const int c = lc0 + 4 * u;
            *(float4*)(KVs + lr * 132 + c) =
                *(const float4*)(vp + (size_t)(j0 + lr) * HH + c);
        }

        // row max partials
        {
            const int r = tid >> 2, part = tid & 3;
            float mx = -CUDART_INF_F;
#pragma unroll
            for (int k2 = 0; k2 < 16; k2++)
                mx = fmaxf(mx, Ss[r * 65 + part * 16 + k2]);
            red[r * 4 + part] = mx;
        }
        __syncthreads();
        if (tid < 64) {
            const float mo = m_sh[tid];
            float mn = fmaxf(fmaxf(red[tid * 4 + 0], red[tid * 4 + 1]),
                             fmaxf(red[tid * 4 + 2], red[tid * 4 + 3]));
            mn = fmaxf(mo, mn);
            m_sh[tid] = mn;
            f_sh[tid] = __expf(mo - mn);
        }
        __syncthreads();

        // exp + row-sum partials; rescale O
        {
            const int r = tid >> 2, part = tid & 3;
            const float mrow = m_sh[r];
            float ssum = 0.f;
#pragma unroll
            for (int k2 = 0; k2 < 16; k2++) {
                const int idx = r * 65 + part * 16 + k2;
                const float p = __expf(Ss[idx] - mrow);
                Ss[idx] = p;
                ssum += p;
            }
            red[r * 4 + part] = ssum;
        }
#pragma unroll
        for (int r = 0; r < 4; r++) {
            const float f = f_sh[ty + 16 * r];
#pragma unroll
            for (int i = 0; i < 8; i++) acc[r][i] *= f;
        }
        __syncthreads();

        if (tid < 64) {
            l_sh[tid] = l_sh[tid] * f_sh[tid] +
                        red[tid * 4 + 0] + red[tid * 4 + 1] +
                        red[tid * 4 + 2] + red[tid * 4 + 3];
        }

        // O += P @ V
#pragma unroll 2
        for (int j = 0; j < 64; j++) {
            float p[4], v[8];
#pragma unroll
            for (int r = 0; r < 4; r++)
                p[r] = Ss[(ty + 16 * r) * 65 + j];
#pragma unroll
            for (int i = 0; i < 8; i++)
                v[i] = KVs[j * 132 + tx + 16 * i];
#pragma unroll
            for (int r = 0; r < 4; r++)
#pragma unroll
                for (int i = 0; i < 8; i++)
                    acc[r][i] = fmaf(p[r], v[i], acc[r][i]);
        }
    }

    __syncthreads();

    // write unnormalized partial + (m, l)
    const size_t pbase = ((size_t)(b * 32 + qt) * 4 + ch);
    float* po = g_po + pbase * 64 * HH;
#pragma unroll
    for (int r = 0; r < 4; r++)
#pragma unroll
        for (int i = 0; i < 8; i++)
            po[(size_t)(ty + 16 * r) * HH + tx + 16 * i] = acc[r][i];
    if (tid < 64) {
        g_pm[pbase * 64 + tid] = m_sh[tid];
        g_pl[pbase * 64 + tid] = l_sh[tid];
    }
}

// ---------------------------------------------------------------------------
// Combine partials: out = (sum_c e^{m_c - M} O_c) / (sum_c e^{m_c - M} l_c)
// ---------------------------------------------------------------------------
__global__ __launch_bounds__(256) void combine_kernel(float* __restrict__ out)
{
    const int qt = blockIdx.x;
    const int b  = blockIdx.y;
    const int nc = (qt + 8) >> 3;   // number of chunks for this qtile

    const int tid = threadIdx.x;
    const int r  = tid >> 2;        // 0..63
    const int cb = (tid & 3) * 32;  // 0,32,64,96

    const size_t pbase = (size_t)(b * 32 + qt) * 4;

    float M = -CUDART_INF_F;
    for (int c = 0; c < nc; c++)
        M = fmaxf(M, g_pm[(pbase + c) * 64 + r]);

    float w[4];
    float l = 0.f;
    for (int c = 0; c < nc; c++) {
        w[c] = __expf(g_pm[(pbase + c) * 64 + r] - M);
        l += w[c] * g_pl[(pbase + c) * 64 + r];
    }
    const float inv = 1.f / l;

    float* op = out + ((size_t)b * TT + qt * 64 + r) * HH;
#pragma unroll
    for (int u = 0; u < 8; u++) {
        float ox = 0.f, oy = 0.f, oz = 0.f, ow = 0.f;
        for (int c = 0; c < nc; c++) {
            const float4 p = *(const float4*)(g_po +
                ((pbase + c) * 64 + r) * HH + cb + 4 * u);
            ox += w[c] * p.x; oy += w[c] * p.y;
            oz += w[c] * p.z; ow += w[c] * p.w;
        }
        *(float4*)(op + cb + 4 * u) =
            make_float4(ox * inv, oy * inv, oz * inv, ow * inv);
    }
}

// ---------------------------------------------------------------------------
extern "C" void kernel_launch(void* const* d_in, const int* in_sizes, int n_in,
                              void* d_out, int out_size)
{
    (void)in_sizes; (void)n_in; (void)out_size;
    const float* x  = (const float*)d_in[0];
    const float* Wq = (const float*)d_in[1];
    const float* Wk = (const float*)d_in[2];
    const float* Wv = (const float*)d_in[3];
    float* out = (float*)d_out;

    const int proj_smem = PROJ_SMEM_U32 * (int)sizeof(uint32_t);  // 53248
    cudaFuncSetAttribute(proj_kernel,
                         cudaFuncAttributeMaxDynamicSharedMemorySize,
                         proj_smem);
    dim3 pgrid(TT * BB / 64, 3);
    proj_kernel<<<pgrid, 256, proj_smem>>>(x, Wq, Wk, Wv);

    const int attn_smem = ATT_SMEM_FLOATS * (int)sizeof(float);   // 84224
    cudaFuncSetAttribute(attn_kernel,
                         cudaFuncAttributeMaxDynamicSharedMemorySize,
                         attn_smem);
    dim3 agrid(32, BB, 4);
    attn_kernel<<<agrid, 256, attn_smem>>>();

    dim3 cgrid(32, BB);
    combine_kernel<<<cgrid, 256>>>(out);
}

// round 4
// speedup vs baseline: 1.9765x; 1.9765x over previous
#include <cuda_runtime.h>
#include <math_constants.h>
#include <cstdint>

#define BB 4
#define TT 2048
#define CC 1024
#define HH 128
#define BT (BB * TT)

// packed bf16-pair planes (one u32 = 2 adjacent bf16)
__device__ uint32_t g_xh[BT * CC / 2], g_xl[BT * CC / 2];
__device__ uint32_t g_wh[3 * CC * HH / 2], g_wl[3 * CC * HH / 2];
__device__ uint32_t g_qh[BT * HH / 2], g_ql[BT * HH / 2];
__device__ uint32_t g_kh[BT * HH / 2], g_kl[BT * HH / 2];
__device__ uint32_t g_vh[BT * HH / 2], g_vl[BT * HH / 2];
// attention partials: [B][16 qblocks][4 chunks]
__device__ float g_po[BB * 16 * 4 * 128 * HH];
__device__ float g_pm[BB * 16 * 4 * 128];
__device__ float g_pl[BB * 16 * 4 * 128];

// ---------------------------------------------------------------------------
// helpers
// ---------------------------------------------------------------------------
__device__ __forceinline__ uint32_t bf2(float lo, float hi) {
    uint32_t r;
    asm("cvt.rn.bf16x2.f32 %0, %1, %2;" : "=r"(r) : "f"(hi), "f"(lo));
    return r;
}
__device__ __forceinline__ void split2(float a, float b, uint32_t& h, uint32_t& l) {
    h = bf2(a, b);                                   // lower = a, upper = b
    float ah = __uint_as_float(h << 16);
    float bh = __uint_as_float(h & 0xffff0000u);
    l = bf2(a - ah, b - bh);
}
__device__ __forceinline__ void mma16816(float c[4], const uint32_t a[4],
                                         uint32_t b0, uint32_t b1) {
    asm volatile(
        "mma.sync.aligned.m16n8k16.row.col.f32.bf16.bf16.f32 "
        "{%0,%1,%2,%3}, {%4,%5,%6,%7}, {%8,%9}, {%0,%1,%2,%3};"
        : "+f"(c[0]), "+f"(c[1]), "+f"(c[2]), "+f"(c[3])
        : "r"(a[0]), "r"(a[1]), "r"(a[2]), "r"(a[3]), "r"(b0), "r"(b1));
}
__device__ __forceinline__ void ldsm4(uint32_t* r, uint32_t addr) {
    asm volatile("ldmatrix.sync.aligned.m8n8.x4.shared.b16 {%0,%1,%2,%3}, [%4];"
                 : "=r"(r[0]), "=r"(r[1]), "=r"(r[2]), "=r"(r[3]) : "r"(addr));
}
__device__ __forceinline__ void ldsm4t(uint32_t* r, uint32_t addr) {
    asm volatile("ldmatrix.sync.aligned.m8n8.x4.trans.shared.b16 {%0,%1,%2,%3}, [%4];"
                 : "=r"(r[0]), "=r"(r[1]), "=r"(r[2]), "=r"(r[3]) : "r"(addr));
}

// ---------------------------------------------------------------------------
// fp32 -> bf16 hi/lo planes.  mode 0: x ; 1..3: Wq/Wk/Wv
// ---------------------------------------------------------------------------
__global__ void convert_kernel(const float* __restrict__ src, int mode, int n4)
{
    uint32_t *dh, *dl;
    if (mode == 0) { dh = g_xh; dl = g_xl; }
    else { dh = g_wh + (mode - 1) * (CC * HH / 2); dl = g_wl + (mode - 1) * (CC * HH / 2); }
    int i = blockIdx.x * blockDim.x + threadIdx.x;
    if (i >= n4) return;
    float4 v = ((const float4*)src)[i];
    uint32_t h0, l0, h1, l1;
    split2(v.x, v.y, h0, l0);
    split2(v.z, v.w, h1, l1);
    ((uint2*)dh)[i] = make_uint2(h0, h1);
    ((uint2*)dl)[i] = make_uint2(l0, l1);
}

// ---------------------------------------------------------------------------
// Projection GEMM, bf16 mma 3-term split.
// Block 128(M) x 128(N), BK=32.  8 warps = 4(M) x 2(N); warp tile 32x64.
// Epilogue writes q/k/v as bf16 hi/lo (q pre-scaled by 1/32).
// smem pitches: X 80 B/row, W 272 B/row (both conflict-free for LDSM).
// ---------------------------------------------------------------------------
#define XPB 80
#define WPB 272
#define SXH 0
#define SXL 10240
#define SWH 20480
#define SWL 29184
#define PROJ_SMEM 37888

__global__ __launch_bounds__(256) void proj_kernel()
{
    extern __shared__ char ps[];
    const uint32_t sb = (uint32_t)__cvta_generic_to_shared(ps);
    const int tid = threadIdx.x, lane = tid & 31, wid = tid >> 5;
    const int wm = wid & 3, wn = wid >> 2;
    const int g = lane >> 2, tg = lane & 3;
    const int m0 = blockIdx.x * 128;
    const int y = blockIdx.y;

    const uint32_t* wh = g_wh + y * (CC * HH / 2);
    const uint32_t* wl = g_wl + y * (CC * HH / 2);
    uint32_t *oh, *ol;
    if (y == 0)      { oh = g_qh; ol = g_ql; }
    else if (y == 1) { oh = g_kh; ol = g_kl; }
    else             { oh = g_vh; ol = g_vl; }

    float acc[2][8][4];
#pragma unroll
    for (int mt = 0; mt < 2; mt++)
#pragma unroll
        for (int nt = 0; nt < 8; nt++)
#pragma unroll
            for (int i = 0; i < 4; i++) acc[mt][nt][i] = 0.f;

    const uint32_t a_coff = (lane >> 4) * 16;                  // bytes
    const uint32_t b_coff = (uint32_t)(wn * 128 + (lane >> 4) * 16);

    for (int k0 = 0; k0 < CC; k0 += 32) {
        __syncthreads();
#pragma unroll
        for (int i = 0; i < 2; i++) {        // X tile 128x32 (2 planes)
            int s = tid + i * 256;
            int row = s >> 2, cs = s & 3;
            size_t gi = (size_t)(m0 + row) * 512 + (k0 >> 1) + cs * 4;
            *(uint4*)(ps + SXH + row * XPB + cs * 16) = *(const uint4*)(g_xh + gi);
            *(uint4*)(ps + SXL + row * XPB + cs * 16) = *(const uint4*)(g_xl + gi);
        }
#pragma unroll
        for (int i = 0; i < 2; i++) {        // W tile 32x128 (2 planes)
            int s = tid + i * 256;
            int row = s >> 4, cs = s & 15;
            size_t gi = (size_t)(k0 + row) * 64 + cs * 4;
            *(uint4*)(ps + SWH + row * WPB + cs * 16) = *(const uint4*)(wh + gi);
            *(uint4*)(ps + SWL + row * WPB + cs * 16) = *(const uint4*)(wl + gi);
        }
        __syncthreads();

#pragma unroll
        for (int ks = 0; ks < 2; ks++) {
            uint32_t ah[2][4], al[2][4];
#pragma unroll
            for (int mt = 0; mt < 2; mt++) {
                uint32_t r = wm * 32 + mt * 16 + (lane & 15);
                ldsm4(ah[mt], sb + SXH + r * XPB + ks * 32 + a_coff);
                ldsm4(al[mt], sb + SXL + r * XPB + ks * 32 + a_coff);
            }
#pragma unroll
            for (int np = 0; np < 4; np++) {
                uint32_t bh[4], bl[4];
                uint32_t r = ks * 16 + (lane & 15);
                ldsm4t(bh, sb + SWH + r * WPB + b_coff + np * 32);
                ldsm4t(bl, sb + SWL + r * WPB + b_coff + np * 32);
#pragma unroll
                for (int mt = 0; mt < 2; mt++)
#pragma unroll
                    for (int h2 = 0; h2 < 2; h2++) {
                        float* c = acc[mt][np * 2 + h2];
                        mma16816(c, ah[mt], bh[2 * h2], bh[2 * h2 + 1]);
                        mma16816(c, ah[mt], bl[2 * h2], bl[2 * h2 + 1]);
                        mma16816(c, al[mt], bh[2 * h2], bh[2 * h2 + 1]);
                    }
            }
        }
    }

    const float sc = (y == 0) ? 0.03125f : 1.0f;   // fold C^-0.5 into q
#pragma unroll
    for (int mt = 0; mt < 2; mt++) {
        const int r1 = m0 + wm * 32 + mt * 16 + g;
#pragma unroll
        for (int nt = 0; nt < 8; nt++) {
            const int c = wn * 64 + nt * 8 + 2 * tg;
            uint32_t h, l;
            split2(acc[mt][nt][0] * sc, acc[mt][nt][1] * sc, h, l);
            oh[(size_t)r1 * 64 + (c >> 1)] = h;
            ol[(size_t)r1 * 64 + (c >> 1)] = l;
            split2(acc[mt][nt][2] * sc, acc[mt][nt][3] * sc, h, l);
            oh[(size_t)(r1 + 8) * 64 + (c >> 1)] = h;
            ol[(size_t)(r1 + 8) * 64 + (c >> 1)] = l;
        }
    }
}

// ---------------------------------------------------------------------------
// Flash attention, bf16 mma 3-term split, register-resident Q and P.
// Block = 128 query rows (8 warps x 16 rows) x chunk of <=8 key tiles.
// smem: K_hi/K_lo/V_hi/V_lo [64][128] bf16, pitch 272 B.
// ---------------------------------------------------------------------------
#define SP 272
#define AKH 0
#define AKL 17408
#define AVH 34816
#define AVL 52224
#define ATT_SMEM 69632

__global__ __launch_bounds__(256) void attn_kernel()
{
    const int qb = blockIdx.x;                 // 0..15
    const int b  = blockIdx.y;                 // 0..3
    const int ch = blockIdx.z;                 // 0..3
    const int ntiles = 2 * qb + 2;
    if (ch * 8 >= ntiles) return;

    extern __shared__ char as_[];
    const uint32_t sb = (uint32_t)__cvta_generic_to_shared(as_);
    const int tid = threadIdx.x, lane = tid & 31, w = tid >> 5;
    const int g = lane >> 2, tg = lane & 3;
    const int r0 = qb * 128;

    // stage Q hi at [0, 34816), Q lo at [34816, 69632); then to registers
    {
        const uint32_t* sh = g_qh + (size_t)b * TT * 64;
        const uint32_t* sl = g_ql + (size_t)b * TT * 64;
#pragma unroll
        for (int i = 0; i < 8; i++) {
            int s = tid + i * 256;
            int row = s >> 4, cs = s & 15;
            size_t gi = (size_t)(r0 + row) * 64 + cs * 4;
            *(uint4*)(as_ + row * SP + cs * 16)       = *(const uint4*)(sh + gi);
            *(uint4*)(as_ + AVH + row * SP + cs * 16) = *(const uint4*)(sl + gi);
        }
    }
    __syncthreads();
    uint32_t qh[8][4], ql[8][4];
    {
        const uint32_t br = w * 16 + (lane & 15);
        const uint32_t co = (lane >> 4) * 16;
#pragma unroll
        for (int ks = 0; ks < 8; ks++) {
            ldsm4(qh[ks], sb + br * SP + ks * 32 + co);
            ldsm4(ql[ks], sb + AVH + br * SP + ks * 32 + co);
        }
    }

    float o[16][4];
#pragma unroll
    for (int nt = 0; nt < 16; nt++)
#pragma unroll
        for (int i = 0; i < 4; i++) o[nt][i] = 0.f;
    float m0 = -CUDART_INF_F, m1 = -CUDART_INF_F, l0 = 0.f, l1 = 0.f;

    const uint32_t* khp = g_kh + (size_t)b * TT * 64;
    const uint32_t* klp = g_kl + (size_t)b * TT * 64;
    const uint32_t* vhp = g_vh + (size_t)b * TT * 64;
    const uint32_t* vlp = g_vl + (size_t)b * TT * 64;

    const int jt1 = min(ch * 8 + 8, ntiles);
    for (int jt = ch * 8; jt < jt1; jt++) {
        const int j0 = jt * 64;
        __syncthreads();
#pragma unroll
        for (int i = 0; i < 4; i++) {          // K,V tiles (4 planes)
            int s = tid + i * 256;
            int row = s >> 4, cs = s & 15;
            size_t gi = (size_t)(j0 + row) * 64 + cs * 4;
            *(uint4*)(as_ + AKH + row * SP + cs * 16) = *(const uint4*)(khp + gi);
            *(uint4*)(as_ + AKL + row * SP + cs * 16) = *(const uint4*)(klp + gi);
            *(uint4*)(as_ + AVH + row * SP + cs * 16) = *(const uint4*)(vhp + gi);
            *(uint4*)(as_ + AVL + row * SP + cs * 16) = *(const uint4*)(vlp + gi);
        }
        __syncthreads();

        // ---- S = Q K^T (q pre-scaled)
        float s_[8][4];
#pragma unroll
        for (int nt = 0; nt < 8; nt++)
#pragma unroll
            for (int i = 0; i < 4; i++) s_[nt][i] = 0.f;
        {
            const uint32_t kr = (lane & 7);
            const uint32_t kc = (lane >> 3) * 16;
#pragma unroll
            for (int kp = 0; kp < 4; kp++) {
#pragma unroll
                for (int nt = 0; nt < 8; nt++) {
                    uint32_t kh4[4], kl4[4];
                    uint32_t ro = (nt * 8 + kr) * SP + kp * 64 + kc;
                    ldsm4(kh4, sb + AKH + ro);
                    ldsm4(kl4, sb + AKL + ro);
                    mma16816(s_[nt], qh[2 * kp],     kh4[0], kh4[1]);
                    mma16816(s_[nt], qh[2 * kp],     kl4[0], kl4[1]);
                    mma16816(s_[nt], ql[2 * kp],     kh4[0], kh4[1]);
                    mma16816(s_[nt], qh[2 * kp + 1], kh4[2], kh4[3]);
                    mma16816(s_[nt], qh[2 * kp + 1], kl4[2], kl4[3]);
                    mma16816(s_[nt], ql[2 * kp + 1], kh4[2], kh4[3]);
                }
            }
        }

        // ---- causal mask (tiles at/after the diagonal)
        if (jt >= 2 * qb) {
            const int rA = r0 + w * 16 + g, rB = rA + 8;
#pragma unroll
            for (int nt = 0; nt < 8; nt++) {
                const int c0 = j0 + nt * 8 + 2 * tg, c1 = c0 + 1;
                if (c0 > rA) s_[nt][0] = -CUDART_INF_F;
                if (c1 > rA) s_[nt][1] = -CUDART_INF_F;
                if (c0 > rB) s_[nt][2] = -CUDART_INF_F;
                if (c1 > rB) s_[nt][3] = -CUDART_INF_F;
            }
        }

        // ---- online softmax (registers + quad shuffles)
        float mx0 = -CUDART_INF_F, mx1 = -CUDART_INF_F;
#pragma unroll
        for (int nt = 0; nt < 8; nt++) {
            mx0 = fmaxf(mx0, fmaxf(s_[nt][0], s_[nt][1]));
            mx1 = fmaxf(mx1, fmaxf(s_[nt][2], s_[nt][3]));
        }
        mx0 = fmaxf(mx0, __shfl_xor_sync(0xffffffffu, mx0, 1));
        mx0 = fmaxf(mx0, __shfl_xor_sync(0xffffffffu, mx0, 2));
        mx1 = fmaxf(mx1, __shfl_xor_sync(0xffffffffu, mx1, 1));
        mx1 = fmaxf(mx1, __shfl_xor_sync(0xffffffffu, mx1, 2));
        const float mn0 = fmaxf(m0, mx0), mn1 = fmaxf(m1, mx1);
        const float f0 = __expf(m0 - mn0), f1 = __expf(m1 - mn1);
        m0 = mn0; m1 = mn1;
        float ps0 = 0.f, ps1 = 0.f;
#pragma unroll
        for (int nt = 0; nt < 8; nt++) {
            s_[nt][0] = __expf(s_[nt][0] - mn0);
            s_[nt][1] = __expf(s_[nt][1] - mn0);
            s_[nt][2] = __expf(s_[nt][2] - mn1);
            s_[nt][3] = __expf(s_[nt][3] - mn1);
            ps0 += s_[nt][0] + s_[nt][1];
            ps1 += s_[nt][2] + s_[nt][3];
        }
        ps0 += __shfl_xor_sync(0xffffffffu, ps0, 1);
        ps0 += __shfl_xor_sync(0xffffffffu, ps0, 2);
        ps1 += __shfl_xor_sync(0xffffffffu, ps1, 1);
        ps1 += __shfl_xor_sync(0xffffffffu, ps1, 2);
        l0 = l0 * f0 + ps0;
        l1 = l1 * f1 + ps1;
#pragma unroll
        for (int nt = 0; nt < 16; nt++) {
            o[nt][0] *= f0; o[nt][1] *= f0;
            o[nt][2] *= f1; o[nt][3] *= f1;
        }

        // ---- O += P V (P split to bf16 in registers)
#pragma unroll
        for (int ks = 0; ks < 4; ks++) {
            uint32_t pah[4], pal[4];
            split2(s_[2 * ks][0],     s_[2 * ks][1],     pah[0], pal[0]);
            split2(s_[2 * ks][2],     s_[2 * ks][3],     pah[1], pal[1]);
            split2(s_[2 * ks + 1][0], s_[2 * ks + 1][1], pah[2], pal[2]);
            split2(s_[2 * ks + 1][2], s_[2 * ks + 1][3], pah[3], pal[3]);
            const uint32_t vr = (ks * 16 + (lane & 15)) * SP + (lane >> 4) * 16;
#pragma unroll
            for (int np = 0; np < 8; np++) {
                uint32_t vh4[4], vl4[4];
                ldsm4t(vh4, sb + AVH + vr + np * 32);
                ldsm4t(vl4, sb + AVL + vr + np * 32);
                float* c0 = o[2 * np];
                float* c1 = o[2 * np + 1];
                mma16816(c0, pah, vh4[0], vh4[1]);
                mma16816(c0, pah, vl4[0], vl4[1]);
                mma16816(c0, pal, vh4[0], vh4[1]);
                mma16816(c1, pah, vh4[2], vh4[3]);
                mma16816(c1, pah, vl4[2], vl4[3]);
                mma16816(c1, pal, vh4[2], vh4[3]);
            }
        }
    }

    // ---- write unnormalized partial + stats
    const size_t pb = (size_t)((b * 16 + qb) * 4 + ch);
    float* po = g_po + pb * 128 * 128;
    const int rA = w * 16 + g;
#pragma unroll
    for (int nt = 0; nt < 16; nt++) {
        const int c = nt * 8 + 2 * tg;
        *(float2*)(po + (size_t)rA * 128 + c)       = make_float2(o[nt][0], o[nt][1]);
        *(float2*)(po + (size_t)(rA + 8) * 128 + c) = make_float2(o[nt][2], o[nt][3]);
    }
    if (tg == 0) {
        g_pm[pb * 128 + rA] = m0;  g_pm[pb * 128 + rA + 8] = m1;
        g_pl[pb * 128 + rA] = l0;  g_pl[pb * 128 + rA + 8] = l1;
    }
}

// ---------------------------------------------------------------------------
// Combine split-KV partials.
// ---------------------------------------------------------------------------
__global__ __launch_bounds__(256) void combine_kernel(float* __restrict__ out)
{
    const int qb = blockIdx.x, b = blockIdx.y;
    const int nc = min(4, (2 * qb + 2 + 7) >> 3);
    const int tid = threadIdx.x;
    const int row = tid >> 1, half = (tid & 1) * 64;
    const size_t pb = (size_t)(b * 16 + qb) * 4;

    float mv[4], M = -CUDART_INF_F;
    for (int c = 0; c < nc; c++) {
        mv[c] = g_pm[(pb + c) * 128 + row];
        M = fmaxf(M, mv[c]);
    }
    float wg[4], l = 0.f;
    for (int c = 0; c < nc; c++) {
        wg[c] = __expf(mv[c] - M);
        l += wg[c] * g_pl[(pb + c) * 128 + row];
    }
    const float inv = 1.f / l;

    float* op = out + ((size_t)b * TT + qb * 128 + row) * HH + half;
#pragma unroll
    for (int u = 0; u < 16; u++) {
        float ox = 0.f, oy = 0.f, oz = 0.f, ow = 0.f;
        for (int c = 0; c < nc; c++) {
            const float4 p = *(const float4*)(g_po +
                ((pb + c) * 128 + row) * 128 + half + 4 * u);
            ox += wg[c] * p.x; oy += wg[c] * p.y;
            oz += wg[c] * p.z; ow += wg[c] * p.w;
        }
        *(float4*)(op + 4 * u) = make_float4(ox * inv, oy * inv, oz * inv, ow * inv);
    }
}

// ---------------------------------------------------------------------------
extern "C" void kernel_launch(void* const* d_in, const int* in_sizes, int n_in,
                              void* d_out, int out_size)
{
    (void)in_sizes; (void)n_in; (void)out_size;
    const float* x  = (const float*)d_in[0];
    const float* Wq = (const float*)d_in[1];
    const float* Wk = (const float*)d_in[2];
    const float* Wv = (const float*)d_in[3];
    float* out = (float*)d_out;

    const int n4x = BT * CC / 4;                  // 2097152
    const int n4w = CC * HH / 4;                  // 32768
    convert_kernel<<<n4x / 256, 256>>>(x, 0, n4x);
    convert_kernel<<<n4w / 256, 256>>>(Wq, 1, n4w);
    convert_kernel<<<n4w / 256, 256>>>(Wk, 2, n4w);
    convert_kernel<<<n4w / 256, 256>>>(Wv, 3, n4w);

    cudaFuncSetAttribute(proj_kernel,
                         cudaFuncAttributeMaxDynamicSharedMemorySize, PROJ_SMEM);
    dim3 pgrid(BT / 128, 3);
    proj_kernel<<<pgrid, 256, PROJ_SMEM>>>();

    cudaFuncSetAttribute(attn_kernel,
                         cudaFuncAttributeMaxDynamicSharedMemorySize, ATT_SMEM);
    dim3 agrid(16, BB, 4);
    attn_kernel<<<agrid, 256, ATT_SMEM>>>();

    dim3 cgrid(16, BB);
    combine_kernel<<<cgrid, 256>>>(out);
}

// round 5
// speedup vs baseline: 2.2241x; 1.1253x over previous
#include <cuda_runtime.h>
#include <math_constants.h>
#include <cstdint>

#define BB 4
#define TT 2048
#define CC 1024
#define HH 128
#define BT (BB * TT)

// packed bf16-pair planes (one u32 = 2 adjacent bf16)
__device__ uint32_t g_xh[BT * CC / 2], g_xl[BT * CC / 2];
__device__ uint32_t g_wh[3 * CC * HH / 2], g_wl[3 * CC * HH / 2];
__device__ uint32_t g_qh[BT * HH / 2], g_ql[BT * HH / 2];
__device__ uint32_t g_kh[BT * HH / 2], g_kl[BT * HH / 2];
__device__ uint32_t g_vh[BT * HH / 2], g_vl[BT * HH / 2];
// attention partials: [B][16 qblocks][4 chunks]
__device__ float g_po[BB * 16 * 4 * 128 * HH];
__device__ float g_pm[BB * 16 * 4 * 128];
__device__ float g_pl[BB * 16 * 4 * 128];

// ---------------------------------------------------------------------------
// helpers
// ---------------------------------------------------------------------------
__device__ __forceinline__ uint32_t bf2(float lo, float hi) {
    uint32_t r;
    asm("cvt.rn.bf16x2.f32 %0, %1, %2;" : "=r"(r) : "f"(hi), "f"(lo));
    return r;
}
__device__ __forceinline__ void split2(float a, float b, uint32_t& h, uint32_t& l) {
    h = bf2(a, b);
    float ah = __uint_as_float(h << 16);
    float bh = __uint_as_float(h & 0xffff0000u);
    l = bf2(a - ah, b - bh);
}
__device__ __forceinline__ void mma16816(float c[4], const uint32_t a[4],
                                         uint32_t b0, uint32_t b1) {
    asm volatile(
        "mma.sync.aligned.m16n8k16.row.col.f32.bf16.bf16.f32 "
        "{%0,%1,%2,%3}, {%4,%5,%6,%7}, {%8,%9}, {%0,%1,%2,%3};"
        : "+f"(c[0]), "+f"(c[1]), "+f"(c[2]), "+f"(c[3])
        : "r"(a[0]), "r"(a[1]), "r"(a[2]), "r"(a[3]), "r"(b0), "r"(b1));
}
__device__ __forceinline__ void ldsm4(uint32_t* r, uint32_t addr) {
    asm volatile("ldmatrix.sync.aligned.m8n8.x4.shared.b16 {%0,%1,%2,%3}, [%4];"
                 : "=r"(r[0]), "=r"(r[1]), "=r"(r[2]), "=r"(r[3]) : "r"(addr));
}
__device__ __forceinline__ void ldsm4t(uint32_t* r, uint32_t addr) {
    asm volatile("ldmatrix.sync.aligned.m8n8.x4.trans.shared.b16 {%0,%1,%2,%3}, [%4];"
                 : "=r"(r[0]), "=r"(r[1]), "=r"(r[2]), "=r"(r[3]) : "r"(addr));
}
__device__ __forceinline__ void cpa16(uint32_t s, const void* g) {
    asm volatile("cp.async.cg.shared.global [%0], [%1], 16;" :: "r"(s), "l"(g));
}
__device__ __forceinline__ void cpa_commit() { asm volatile("cp.async.commit_group;"); }
__device__ __forceinline__ void cpa_wait0()  { asm volatile("cp.async.wait_group 0;"); }
__device__ __forceinline__ void cpa_wait1()  { asm volatile("cp.async.wait_group 1;"); }

// ---------------------------------------------------------------------------
// fp32 -> bf16 hi/lo planes, single launch for x + Wq + Wk + Wv
// ---------------------------------------------------------------------------
#define N4X (BT * CC / 4)
#define N4W (CC * HH / 4)

__global__ void convert_kernel(const float* __restrict__ x,
                               const float* __restrict__ wq,
                               const float* __restrict__ wk,
                               const float* __restrict__ wv)
{
    int i = blockIdx.x * blockDim.x + threadIdx.x;
    const float* src;
    uint32_t *dh, *dl;
    int idx;
    if (i < N4X) {
        src = x; idx = i; dh = g_xh; dl = g_xl;
    } else {
        int j = i - N4X;
        if (j >= 3 * N4W) return;
        int w = j / N4W; idx = j - w * N4W;
        src = (w == 0) ? wq : (w == 1) ? wk : wv;
        dh = g_wh + w * (CC * HH / 2);
        dl = g_wl + w * (CC * HH / 2);
    }
    float4 v = ((const float4*)src)[idx];
    uint32_t h0, l0, h1, l1;
    split2(v.x, v.y, h0, l0);
    split2(v.z, v.w, h1, l1);
    ((uint2*)dh)[idx] = make_uint2(h0, h1);
    ((uint2*)dl)[idx] = make_uint2(l0, l1);
}

// ---------------------------------------------------------------------------
// Projection GEMM, bf16 mma 3-term split, cp.async double-buffered.
// Block 128(M) x 128(N), BK=32.  8 warps = 4(M) x 2(N); warp tile 32x64.
// ---------------------------------------------------------------------------
#define XPB 80
#define WPB 272
#define SXH 0
#define SXL 10240
#define SWH 20480
#define SWL 29184
#define PROJ_BUF 37888
#define PROJ_SMEM (2 * PROJ_BUF)

__global__ __launch_bounds__(256) void proj_kernel()
{
    extern __shared__ char ps[];
    const uint32_t sb = (uint32_t)__cvta_generic_to_shared(ps);
    const int tid = threadIdx.x, lane = tid & 31, wid = tid >> 5;
    const int wm = wid & 3, wn = wid >> 2;
    const int g = lane >> 2, tg = lane & 3;
    const int m0 = blockIdx.x * 128;
    const int y = blockIdx.y;

    const uint32_t* wh = g_wh + y * (CC * HH / 2);
    const uint32_t* wl = g_wl + y * (CC * HH / 2);
    uint32_t *oh, *ol;
    if (y == 0)      { oh = g_qh; ol = g_ql; }
    else if (y == 1) { oh = g_kh; ol = g_kl; }
    else             { oh = g_vh; ol = g_vl; }

    float acc[2][8][4];
#pragma unroll
    for (int mt = 0; mt < 2; mt++)
#pragma unroll
        for (int nt = 0; nt < 8; nt++)
#pragma unroll
            for (int i = 0; i < 4; i++) acc[mt][nt][i] = 0.f;

    const uint32_t a_coff = (lane >> 4) * 16;
    const uint32_t b_coff = (uint32_t)(wn * 128 + (lane >> 4) * 16);

    // async tile loader for K-step k0 into buffer offset bo
    auto load_k = [&](int k0, uint32_t bo) {
#pragma unroll
        for (int i = 0; i < 2; i++) {            // X tile 128x32 (2 planes)
            int s = tid + i * 256;
            int row = s >> 2, cs = s & 3;
            size_t gi = (size_t)(m0 + row) * 512 + (k0 >> 1) + cs * 4;
            cpa16(sb + bo + SXH + row * XPB + cs * 16, g_xh + gi);
            cpa16(sb + bo + SXL + row * XPB + cs * 16, g_xl + gi);
        }
#pragma unroll
        for (int i = 0; i < 2; i++) {            // W tile 32x128 (2 planes)
            int s = tid + i * 256;
            int row = s >> 4, cs = s & 15;
            size_t gi = (size_t)(k0 + row) * 64 + cs * 4;
            cpa16(sb + bo + SWH + row * WPB + cs * 16, wh + gi);
            cpa16(sb + bo + SWL + row * WPB + cs * 16, wl + gi);
        }
    };

    load_k(0, 0);
    cpa_commit();

    for (int it = 0; it < 32; it++) {
        const uint32_t bo = (uint32_t)(it & 1) * PROJ_BUF;
        if (it < 31) {
            load_k((it + 1) * 32, bo ^ PROJ_BUF);
            cpa_commit();
            cpa_wait1();
        } else {
            cpa_wait0();
        }
        __syncthreads();

#pragma unroll
        for (int ks = 0; ks < 2; ks++) {
            uint32_t ah[2][4], al[2][4];
#pragma unroll
            for (int mt = 0; mt < 2; mt++) {
                uint32_t r = wm * 32 + mt * 16 + (lane & 15);
                ldsm4(ah[mt], sb + bo + SXH + r * XPB + ks * 32 + a_coff);
                ldsm4(al[mt], sb + bo + SXL + r * XPB + ks * 32 + a_coff);
            }
#pragma unroll
            for (int np = 0; np < 4; np++) {
                uint32_t bh[4], bl[4];
                uint32_t r = ks * 16 + (lane & 15);
                ldsm4t(bh, sb + bo + SWH + r * WPB + b_coff + np * 32);
                ldsm4t(bl, sb + bo + SWL + r * WPB + b_coff + np * 32);
#pragma unroll
                for (int mt = 0; mt < 2; mt++)
#pragma unroll
                    for (int h2 = 0; h2 < 2; h2++) {
                        float* c = acc[mt][np * 2 + h2];
                        mma16816(c, ah[mt], bh[2 * h2], bh[2 * h2 + 1]);
                        mma16816(c, ah[mt], bl[2 * h2], bl[2 * h2 + 1]);
                        mma16816(c, al[mt], bh[2 * h2], bh[2 * h2 + 1]);
                    }
            }
        }
        __syncthreads();
    }

    const float sc = (y == 0) ? 0.03125f : 1.0f;   // fold C^-0.5 into q
#pragma unroll
    for (int mt = 0; mt < 2; mt++) {
        const int r1 = m0 + wm * 32 + mt * 16 + g;
#pragma unroll
        for (int nt = 0; nt < 8; nt++) {
            const int c = wn * 64 + nt * 8 + 2 * tg;
            uint32_t h, l;
            split2(acc[mt][nt][0] * sc, acc[mt][nt][1] * sc, h, l);
            oh[(size_t)r1 * 64 + (c >> 1)] = h;
            ol[(size_t)r1 * 64 + (c >> 1)] = l;
            split2(acc[mt][nt][2] * sc, acc[mt][nt][3] * sc, h, l);
            oh[(size_t)(r1 + 8) * 64 + (c >> 1)] = h;
            ol[(size_t)(r1 + 8) * 64 + (c >> 1)] = l;
        }
    }
}

// ---------------------------------------------------------------------------
// Flash attention, bf16 mma 3-term split, cp.async double-buffered K/V.
// Block = 128 query rows x chunk of <=8 key tiles (64 keys each).
// smem: 2 buffers x {K_hi,K_lo,V_hi,V_lo}[64][128] bf16, pitch 272 B.
// Single-chunk blocks (qb<=3) normalize and write out directly.
// ---------------------------------------------------------------------------
#define SP 272
#define AKH 0
#define AKL 17408
#define AVH 34816
#define AVL 52224
#define ATT_BUF 69632
#define ATT_SMEM (2 * ATT_BUF)

__global__ __launch_bounds__(256) void attn_kernel(float* __restrict__ out)
{
    const int qb = blockIdx.x;                 // 0..15
    const int b  = blockIdx.y;                 // 0..3
    const int ch = blockIdx.z;                 // 0..3
    const int ntiles = 2 * qb + 2;
    if (ch * 8 >= ntiles) return;

    extern __shared__ char as_[];
    const uint32_t sb = (uint32_t)__cvta_generic_to_shared(as_);
    const int tid = threadIdx.x, lane = tid & 31, w = tid >> 5;
    const int g = lane >> 2, tg = lane & 3;
    const int r0 = qb * 128;

    // ---- stage Q into buffer0 (hi at 0, lo at AVH), async then to registers
    {
        const uint32_t* sh = g_qh + (size_t)b * TT * 64;
        const uint32_t* sl = g_ql + (size_t)b * TT * 64;
#pragma unroll
        for (int i = 0; i < 8; i++) {
            int s = tid + i * 256;
            int row = s >> 4, cs = s & 15;
            size_t gi = (size_t)(r0 + row) * 64 + cs * 4;
            cpa16(sb + row * SP + cs * 16, sh + gi);
            cpa16(sb + AVH + row * SP + cs * 16, sl + gi);
        }
        cpa_commit();
        cpa_wait0();
    }
    __syncthreads();
    uint32_t qh[8][4], ql[8][4];
    {
        const uint32_t br = w * 16 + (lane & 15);
        const uint32_t co = (lane >> 4) * 16;
#pragma unroll
        for (int ks = 0; ks < 8; ks++) {
            ldsm4(qh[ks], sb + br * SP + ks * 32 + co);
            ldsm4(ql[ks], sb + AVH + br * SP + ks * 32 + co);
        }
    }
    __syncthreads();   // Q in registers; buffer0 reusable

    float o[16][4];
#pragma unroll
    for (int nt = 0; nt < 16; nt++)
#pragma unroll
        for (int i = 0; i < 4; i++) o[nt][i] = 0.f;
    float m0 = -CUDART_INF_F, m1 = -CUDART_INF_F, l0 = 0.f, l1 = 0.f;

    const uint32_t* khp = g_kh + (size_t)b * TT * 64;
    const uint32_t* klp = g_kl + (size_t)b * TT * 64;
    const uint32_t* vhp = g_vh + (size_t)b * TT * 64;
    const uint32_t* vlp = g_vl + (size_t)b * TT * 64;

    auto load_tile = [&](int j0, uint32_t bo) {
#pragma unroll
        for (int i = 0; i < 4; i++) {
            int s = tid + i * 256;
            int row = s >> 4, cs = s & 15;
            size_t gi = (size_t)(j0 + row) * 64 + cs * 4;
            uint32_t so = bo + row * SP + cs * 16;
            cpa16(sb + so + AKH, khp + gi);
            cpa16(sb + so + AKL, klp + gi);
            cpa16(sb + so + AVH, vhp + gi);
            cpa16(sb + so + AVL, vlp + gi);
        }
    };

    const int jt0 = ch * 8;
    const int n = min(jt0 + 8, ntiles) - jt0;

    load_tile(jt0 * 64, 0);
    cpa_commit();

    for (int it = 0; it < n; it++) {
        const int jt = jt0 + it;
        const int j0 = jt * 64;
        const uint32_t bo = (uint32_t)(it & 1) * ATT_BUF;
        if (it + 1 < n) {
            load_tile((jt + 1) * 64, bo ^ ATT_BUF);
            cpa_commit();
            cpa_wait1();
        } else {
            cpa_wait0();
        }
        __syncthreads();

        // ---- S = Q K^T (q pre-scaled by 1/32)
        float s_[8][4];
#pragma unroll
        for (int nt = 0; nt < 8; nt++)
#pragma unroll
            for (int i = 0; i < 4; i++) s_[nt][i] = 0.f;
        {
            const uint32_t kr = (lane & 7);
            const uint32_t kc = (lane >> 3) * 16;
#pragma unroll
            for (int kp = 0; kp < 4; kp++) {
#pragma unroll
                for (int nt = 0; nt < 8; nt++) {
                    uint32_t kh4[4], kl4[4];
                    uint32_t ro = bo + (nt * 8 + kr) * SP + kp * 64 + kc;
                    ldsm4(kh4, sb + AKH + ro);
                    ldsm4(kl4, sb + AKL + ro);
                    mma16816(s_[nt], qh[2 * kp],     kh4[0], kh4[1]);
                    mma16816(s_[nt], qh[2 * kp],     kl4[0], kl4[1]);
                    mma16816(s_[nt], ql[2 * kp],     kh4[0], kh4[1]);
                    mma16816(s_[nt], qh[2 * kp + 1], kh4[2], kh4[3]);
                    mma16816(s_[nt], qh[2 * kp + 1], kl4[2], kl4[3]);
                    mma16816(s_[nt], ql[2 * kp + 1], kh4[2], kh4[3]);
                }
            }
        }

        // ---- causal mask (tiles at/after the diagonal)
        if (jt >= 2 * qb) {
            const int rA = r0 + w * 16 + g, rB = rA + 8;
#pragma unroll
            for (int nt = 0; nt < 8; nt++) {
                const int c0 = j0 + nt * 8 + 2 * tg, c1 = c0 + 1;
                if (c0 > rA) s_[nt][0] = -CUDART_INF_F;
                if (c1 > rA) s_[nt][1] = -CUDART_INF_F;
                if (c0 > rB) s_[nt][2] = -CUDART_INF_F;
                if (c1 > rB) s_[nt][3] = -CUDART_INF_F;
            }
        }

        // ---- online softmax (registers + quad shuffles)
        float mx0 = -CUDART_INF_F, mx1 = -CUDART_INF_F;
#pragma unroll
        for (int nt = 0; nt < 8; nt++) {
            mx0 = fmaxf(mx0, fmaxf(s_[nt][0], s_[nt][1]));
            mx1 = fmaxf(mx1, fmaxf(s_[nt][2], s_[nt][3]));
        }
        mx0 = fmaxf(mx0, __shfl_xor_sync(0xffffffffu, mx0, 1));
        mx0 = fmaxf(mx0, __shfl_xor_sync(0xffffffffu, mx0, 2));
        mx1 = fmaxf(mx1, __shfl_xor_sync(0xffffffffu, mx1, 1));
        mx1 = fmaxf(mx1, __shfl_xor_sync(0xffffffffu, mx1, 2));
        const float mn0 = fmaxf(m0, mx0), mn1 = fmaxf(m1, mx1);
        const float f0 = __expf(m0 - mn0), f1 = __expf(m1 - mn1);
        m0 = mn0; m1 = mn1;
        float ps0 = 0.f, ps1 = 0.f;
#pragma unroll
        for (int nt = 0; nt < 8; nt++) {
            s_[nt][0] = __expf(s_[nt][0] - mn0);
            s_[nt][1] = __expf(s_[nt][1] - mn0);
            s_[nt][2] = __expf(s_[nt][2] - mn1);
            s_[nt][3] = __expf(s_[nt][3] - mn1);
            ps0 += s_[nt][0] + s_[nt][1];
            ps1 += s_[nt][2] + s_[nt][3];
        }
        ps0 += __shfl_xor_sync(0xffffffffu, ps0, 1);
        ps0 += __shfl_xor_sync(0xffffffffu, ps0, 2);
        ps1 += __shfl_xor_sync(0xffffffffu, ps1, 1);
        ps1 += __shfl_xor_sync(0xffffffffu, ps1, 2);
        l0 = l0 * f0 + ps0;
        l1 = l1 * f1 + ps1;
#pragma unroll
        for (int nt = 0; nt < 16; nt++) {
            o[nt][0] *= f0; o[nt][1] *= f0;
            o[nt][2] *= f1; o[nt][3] *= f1;
        }

        // ---- O += P V (P split to bf16 in registers)
#pragma unroll
        for (int ks = 0; ks < 4; ks++) {
            uint32_t pah[4], pal[4];
            split2(s_[2 * ks][0],     s_[2 * ks][1],     pah[0], pal[0]);
            split2(s_[2 * ks][2],     s_[2 * ks][3],     pah[1], pal[1]);
            split2(s_[2 * ks + 1][0], s_[2 * ks + 1][1], pah[2], pal[2]);
            split2(s_[2 * ks + 1][2], s_[2 * ks + 1][3], pah[3], pal[3]);
            const uint32_t vr = bo + (ks * 16 + (lane & 15)) * SP + (lane >> 4) * 16;
#pragma unroll
            for (int np = 0; np < 8; np++) {
                uint32_t vh4[4], vl4[4];
                ldsm4t(vh4, sb + AVH + vr + np * 32);
                ldsm4t(vl4, sb + AVL + vr + np * 32);
                float* c0 = o[2 * np];
                float* c1 = o[2 * np + 1];
                mma16816(c0, pah, vh4[0], vh4[1]);
                mma16816(c0, pah, vl4[0], vl4[1]);
                mma16816(c0, pal, vh4[0], vh4[1]);
                mma16816(c1, pah, vh4[2], vh4[3]);
                mma16816(c1, pah, vl4[2], vl4[3]);
                mma16816(c1, pal, vh4[2], vh4[3]);
            }
        }
        __syncthreads();
    }

    const int rA = w * 16 + g;
    if (ntiles <= 8) {
        // single chunk: normalize and write final output directly
        const float inv0 = 1.f / l0, inv1 = 1.f / l1;
        float* op = out + ((size_t)b * TT + r0) * HH;
#pragma unroll
        for (int nt = 0; nt < 16; nt++) {
            const int c = nt * 8 + 2 * tg;
            *(float2*)(op + (size_t)rA * HH + c) =
                make_float2(o[nt][0] * inv0, o[nt][1] * inv0);
            *(float2*)(op + (size_t)(rA + 8) * HH + c) =
                make_float2(o[nt][2] * inv1, o[nt][3] * inv1);
        }
    } else {
        const size_t pb = (size_t)((b * 16 + qb) * 4 + ch);
        float* po = g_po + pb * 128 * 128;
#pragma unroll
        for (int nt = 0; nt < 16; nt++) {
            const int c = nt * 8 + 2 * tg;
            *(float2*)(po + (size_t)rA * 128 + c)       = make_float2(o[nt][0], o[nt][1]);
            *(float2*)(po + (size_t)(rA + 8) * 128 + c) = make_float2(o[nt][2], o[nt][3]);
        }
        if (tg == 0) {
            g_pm[pb * 128 + rA] = m0;  g_pm[pb * 128 + rA + 8] = m1;
            g_pl[pb * 128 + rA] = l0;  g_pl[pb * 128 + rA + 8] = l1;
        }
    }
}

// ---------------------------------------------------------------------------
// Combine split-KV partials (qb >= 4 only).
// ---------------------------------------------------------------------------
__global__ __launch_bounds__(256) void combine_kernel(float* __restrict__ out)
{
    const int qb = blockIdx.x + 4, b = blockIdx.y;
    const int nc = min(4, (2 * qb + 2 + 7) >> 3);
    const int tid = threadIdx.x;
    const int row = tid >> 1, half = (tid & 1) * 64;
    const size_t pb = (size_t)(b * 16 + qb) * 4;

    float mv[4], M = -CUDART_INF_F;
    for (int c = 0; c < nc; c++) {
        mv[c] = g_pm[(pb + c) * 128 + row];
        M = fmaxf(M, mv[c]);
    }
    float wg[4], l = 0.f;
    for (int c = 0; c < nc; c++) {
        wg[c] = __expf(mv[c] - M);
        l += wg[c] * g_pl[(pb + c) * 128 + row];
    }
    const float inv = 1.f / l;

    float* op = out + ((size_t)b * TT + qb * 128 + row) * HH + half;
#pragma unroll
    for (int u = 0; u < 16; u++) {
        float ox = 0.f, oy = 0.f, oz = 0.f, ow = 0.f;
        for (int c = 0; c < nc; c++) {
            const float4 p = *(const float4*)(g_po +
                ((pb + c) * 128 + row) * 128 + half + 4 * u);
            ox += wg[c] * p.x; oy += wg[c] * p.y;
            oz += wg[c] * p.z; ow += wg[c] * p.w;
        }
        *(float4*)(op + 4 * u) = make_float4(ox * inv, oy * inv, oz * inv, ow * inv);
    }
}

// ---------------------------------------------------------------------------
extern "C" void kernel_launch(void* const* d_in, const int* in_sizes, int n_in,
                              void* d_out, int out_size)
{
    (void)in_sizes; (void)n_in; (void)out_size;
    const float* x  = (const float*)d_in[0];
    const float* Wq = (const float*)d_in[1];
    const float* Wk = (const float*)d_in[2];
    const float* Wv = (const float*)d_in[3];
    float* out = (float*)d_out;

    const int ncv = N4X + 3 * N4W;
    convert_kernel<<<(ncv + 255) / 256, 256>>>(x, Wq, Wk, Wv);

    cudaFuncSetAttribute(proj_kernel,
                         cudaFuncAttributeMaxDynamicSharedMemorySize, PROJ_SMEM);
    dim3 pgrid(BT / 128, 3);
    proj_kernel<<<pgrid, 256, PROJ_SMEM>>>();

    cudaFuncSetAttribute(attn_kernel,
                         cudaFuncAttributeMaxDynamicSharedMemorySize, ATT_SMEM);
    dim3 agrid(16, BB, 4);
    attn_kernel<<<agrid, 256, ATT_SMEM>>>(out);

    dim3 cgrid(12, BB);
    combine_kernel<<<cgrid, 256>>>(out);
}

// round 6
// speedup vs baseline: 2.8514x; 1.2821x over previous
#include <cuda_runtime.h>
#include <math_constants.h>
#include <cstdint>

#define BB 4
#define TT 2048
#define CC 1024
#define HH 128
#define BT (BB * TT)

// packed bf16-pair planes (one u32 = 2 adjacent bf16)
__device__ uint32_t g_xh[BT * CC / 2], g_xl[BT * CC / 2];
__device__ uint32_t g_wh[3 * CC * HH / 2], g_wl[3 * CC * HH / 2];
__device__ uint32_t g_qh[BT * HH / 2], g_ql[BT * HH / 2];
__device__ uint32_t g_kh[BT * HH / 2], g_kl[BT * HH / 2];
__device__ uint32_t g_vh[BT * HH / 2], g_vl[BT * HH / 2];
// attention partials: [B][16 qblocks][8 chunks]
__device__ float g_po[BB * 16 * 8 * 128 * HH];
__device__ float g_pm[BB * 16 * 8 * 128];
__device__ float g_pl[BB * 16 * 8 * 128];

// ---------------------------------------------------------------------------
// helpers
// ---------------------------------------------------------------------------
__device__ __forceinline__ uint32_t bf2(float lo, float hi) {
    uint32_t r;
    asm("cvt.rn.bf16x2.f32 %0, %1, %2;" : "=r"(r) : "f"(hi), "f"(lo));
    return r;
}
__device__ __forceinline__ void split2(float a, float b, uint32_t& h, uint32_t& l) {
    h = bf2(a, b);
    float ah = __uint_as_float(h << 16);
    float bh = __uint_as_float(h & 0xffff0000u);
    l = bf2(a - ah, b - bh);
}
__device__ __forceinline__ void mma16816(float c[4], const uint32_t a[4],
                                         uint32_t b0, uint32_t b1) {
    asm volatile(
        "mma.sync.aligned.m16n8k16.row.col.f32.bf16.bf16.f32 "
        "{%0,%1,%2,%3}, {%4,%5,%6,%7}, {%8,%9}, {%0,%1,%2,%3};"
        : "+f"(c[0]), "+f"(c[1]), "+f"(c[2]), "+f"(c[3])
        : "r"(a[0]), "r"(a[1]), "r"(a[2]), "r"(a[3]), "r"(b0), "r"(b1));
}
__device__ __forceinline__ void ldsm4(uint32_t* r, uint32_t addr) {
    asm volatile("ldmatrix.sync.aligned.m8n8.x4.shared.b16 {%0,%1,%2,%3}, [%4];"
                 : "=r"(r[0]), "=r"(r[1]), "=r"(r[2]), "=r"(r[3]) : "r"(addr));
}
__device__ __forceinline__ void ldsm4t(uint32_t* r, uint32_t addr) {
    asm volatile("ldmatrix.sync.aligned.m8n8.x4.trans.shared.b16 {%0,%1,%2,%3}, [%4];"
                 : "=r"(r[0]), "=r"(r[1]), "=r"(r[2]), "=r"(r[3]) : "r"(addr));
}
__device__ __forceinline__ void cpa16(uint32_t s, const void* g) {
    asm volatile("cp.async.cg.shared.global [%0], [%1], 16;" :: "r"(s), "l"(g));
}
__device__ __forceinline__ void cpa_commit() { asm volatile("cp.async.commit_group;"); }
__device__ __forceinline__ void cpa_wait0()  { asm volatile("cp.async.wait_group 0;"); }
__device__ __forceinline__ void cpa_wait1()  { asm volatile("cp.async.wait_group 1;"); }

// ---------------------------------------------------------------------------
// fp32 -> bf16 hi/lo planes, single launch for x + Wq + Wk + Wv
// ---------------------------------------------------------------------------
#define N4X (BT * CC / 4)
#define N4W (CC * HH / 4)

__global__ void convert_kernel(const float* __restrict__ x,
                               const float* __restrict__ wq,
                               const float* __restrict__ wk,
                               const float* __restrict__ wv)
{
    int i = blockIdx.x * blockDim.x + threadIdx.x;
    const float* src;
    uint32_t *dh, *dl;
    int idx;
    if (i < N4X) {
        src = x; idx = i; dh = g_xh; dl = g_xl;
    } else {
        int j = i - N4X;
        if (j >= 3 * N4W) return;
        int w = j / N4W; idx = j - w * N4W;
        src = (w == 0) ? wq : (w == 1) ? wk : wv;
        dh = g_wh + w * (CC * HH / 2);
        dl = g_wl + w * (CC * HH / 2);
    }
    float4 v = ((const float4*)src)[idx];
    uint32_t h0, l0, h1, l1;
    split2(v.x, v.y, h0, l0);
    split2(v.z, v.w, h1, l1);
    ((uint2*)dh)[idx] = make_uint2(h0, h1);
    ((uint2*)dl)[idx] = make_uint2(l0, l1);
}

// ---------------------------------------------------------------------------
// Projection GEMM, bf16 mma 3-term split, cp.async double-buffered.
// Block 64(M) x 128(N), BK=32.  8 warps = 4(M) x 2(N); warp tile 16x64.
// 384 blocks -> better wave balance on 148 SMs.
// ---------------------------------------------------------------------------
#define XPB 80
#define WPB 272
#define SXH 0
#define SXL 5120
#define SWH 10240
#define SWL 18944
#define PROJ_BUF 27648
#define PROJ_SMEM (2 * PROJ_BUF)

__global__ __launch_bounds__(256) void proj_kernel()
{
    extern __shared__ char ps[];
    const uint32_t sb = (uint32_t)__cvta_generic_to_shared(ps);
    const int tid = threadIdx.x, lane = tid & 31, wid = tid >> 5;
    const int wm = wid & 3, wn = wid >> 2;
    const int g = lane >> 2, tg = lane & 3;
    const int m0 = blockIdx.x * 64;
    const int y = blockIdx.y;

    const uint32_t* wh = g_wh + y * (CC * HH / 2);
    const uint32_t* wl = g_wl + y * (CC * HH / 2);
    uint32_t *oh, *ol;
    if (y == 0)      { oh = g_qh; ol = g_ql; }
    else if (y == 1) { oh = g_kh; ol = g_kl; }
    else             { oh = g_vh; ol = g_vl; }

    float acc[8][4];
#pragma unroll
    for (int nt = 0; nt < 8; nt++)
#pragma unroll
        for (int i = 0; i < 4; i++) acc[nt][i] = 0.f;

    const uint32_t a_coff = (lane >> 4) * 16;
    const uint32_t b_coff = (uint32_t)(wn * 128 + (lane >> 4) * 16);

    auto load_k = [&](int k0, uint32_t bo) {
        {   // X tile 64x32 (2 planes): 256 segs, 1 per thread
            int row = tid >> 2, cs = tid & 3;
            size_t gi = (size_t)(m0 + row) * 512 + (k0 >> 1) + cs * 4;
            cpa16(sb + bo + SXH + row * XPB + cs * 16, g_xh + gi);
            cpa16(sb + bo + SXL + row * XPB + cs * 16, g_xl + gi);
        }
#pragma unroll
        for (int i = 0; i < 2; i++) {            // W tile 32x128 (2 planes)
            int s = tid + i * 256;
            int row = s >> 4, cs = s & 15;
            size_t gi = (size_t)(k0 + row) * 64 + cs * 4;
            cpa16(sb + bo + SWH + row * WPB + cs * 16, wh + gi);
            cpa16(sb + bo + SWL + row * WPB + cs * 16, wl + gi);
        }
    };

    load_k(0, 0);
    cpa_commit();

    for (int it = 0; it < 32; it++) {
        const uint32_t bo = (uint32_t)(it & 1) * PROJ_BUF;
        if (it < 31) {
            load_k((it + 1) * 32, bo ^ PROJ_BUF);
            cpa_commit();
            cpa_wait1();
        } else {
            cpa_wait0();
        }
        __syncthreads();

#pragma unroll
        for (int ks = 0; ks < 2; ks++) {
            uint32_t ah[4], al[4];
            {
                uint32_t r = wm * 16 + (lane & 15);
                ldsm4(ah, sb + bo + SXH + r * XPB + ks * 32 + a_coff);
                ldsm4(al, sb + bo + SXL + r * XPB + ks * 32 + a_coff);
            }
#pragma unroll
            for (int np = 0; np < 4; np++) {
                uint32_t bh[4], bl[4];
                uint32_t r = ks * 16 + (lane & 15);
                ldsm4t(bh, sb + bo + SWH + r * WPB + b_coff + np * 32);
                ldsm4t(bl, sb + bo + SWL + r * WPB + b_coff + np * 32);
#pragma unroll
                for (int h2 = 0; h2 < 2; h2++) {
                    float* c = acc[np * 2 + h2];
                    mma16816(c, ah, bh[2 * h2], bh[2 * h2 + 1]);
                    mma16816(c, ah, bl[2 * h2], bl[2 * h2 + 1]);
                    mma16816(c, al, bh[2 * h2], bh[2 * h2 + 1]);
                }
            }
        }
        __syncthreads();
    }

    const float sc = (y == 0) ? 0.03125f : 1.0f;   // fold C^-0.5 into q
    const int r1 = m0 + wm * 16 + g;
#pragma unroll
    for (int nt = 0; nt < 8; nt++) {
        const int c = wn * 64 + nt * 8 + 2 * tg;
        uint32_t h, l;
        split2(acc[nt][0] * sc, acc[nt][1] * sc, h, l);
        oh[(size_t)r1 * 64 + (c >> 1)] = h;
        ol[(size_t)r1 * 64 + (c >> 1)] = l;
        split2(acc[nt][2] * sc, acc[nt][3] * sc, h, l);
        oh[(size_t)(r1 + 8) * 64 + (c >> 1)] = h;
        ol[(size_t)(r1 + 8) * 64 + (c >> 1)] = l;
    }
}

// ---------------------------------------------------------------------------
// Flash attention, bf16 mma 3-term split, cp.async double-buffered K/V.
// Block = 128 query rows x chunk of <=4 key tiles (64 keys each).
// 288 real blocks -> max ~2 per SM -> critical path ~8 tiles.
// Single-chunk blocks (qb<=1) normalize and write out directly.
// ---------------------------------------------------------------------------
#define SP 272
#define AKH 0
#define AKL 17408
#define AVH 34816
#define AVL 52224
#define ATT_BUF 69632
#define ATT_SMEM (2 * ATT_BUF)

__global__ __launch_bounds__(256) void attn_kernel(float* __restrict__ out)
{
    const int qb = blockIdx.x;                 // 0..15
    const int b  = blockIdx.y;                 // 0..3
    const int ch = blockIdx.z;                 // 0..7
    const int ntiles = 2 * qb + 2;
    if (ch * 4 >= ntiles) return;

    extern __shared__ char as_[];
    const uint32_t sb = (uint32_t)__cvta_generic_to_shared(as_);
    const int tid = threadIdx.x, lane = tid & 31, w = tid >> 5;
    const int g = lane >> 2, tg = lane & 3;
    const int r0 = qb * 128;

    // ---- stage Q into buffer0 (hi at 0, lo at AVH), async then to registers
    {
        const uint32_t* sh = g_qh + (size_t)b * TT * 64;
        const uint32_t* sl = g_ql + (size_t)b * TT * 64;
#pragma unroll
        for (int i = 0; i < 8; i++) {
            int s = tid + i * 256;
            int row = s >> 4, cs = s & 15;
            size_t gi = (size_t)(r0 + row) * 64 + cs * 4;
            cpa16(sb + row * SP + cs * 16, sh + gi);
            cpa16(sb + AVH + row * SP + cs * 16, sl + gi);
        }
        cpa_commit();
        cpa_wait0();
    }
    __syncthreads();
    uint32_t qh[8][4], ql[8][4];
    {
        const uint32_t br = w * 16 + (lane & 15);
        const uint32_t co = (lane >> 4) * 16;
#pragma unroll
        for (int ks = 0; ks < 8; ks++) {
            ldsm4(qh[ks], sb + br * SP + ks * 32 + co);
            ldsm4(ql[ks], sb + AVH + br * SP + ks * 32 + co);
        }
    }
    __syncthreads();   // Q in registers; buffer0 reusable

    float o[16][4];
#pragma unroll
    for (int nt = 0; nt < 16; nt++)
#pragma unroll
        for (int i = 0; i < 4; i++) o[nt][i] = 0.f;
    float m0 = -CUDART_INF_F, m1 = -CUDART_INF_F, l0 = 0.f, l1 = 0.f;

    const uint32_t* khp = g_kh + (size_t)b * TT * 64;
    const uint32_t* klp = g_kl + (size_t)b * TT * 64;
    const uint32_t* vhp = g_vh + (size_t)b * TT * 64;
    const uint32_t* vlp = g_vl + (size_t)b * TT * 64;

    auto load_tile = [&](int j0, uint32_t bo) {
#pragma unroll
        for (int i = 0; i < 4; i++) {
            int s = tid + i * 256;
            int row = s >> 4, cs = s & 15;
            size_t gi = (size_t)(j0 + row) * 64 + cs * 4;
            uint32_t so = bo + row * SP + cs * 16;
            cpa16(sb + so + AKH, khp + gi);
            cpa16(sb + so + AKL, klp + gi);
            cpa16(sb + so + AVH, vhp + gi);
            cpa16(sb + so + AVL, vlp + gi);
        }
    };

    const int jt0 = ch * 4;
    const int n = min(jt0 + 4, ntiles) - jt0;

    load_tile(jt0 * 64, 0);
    cpa_commit();

    for (int it = 0; it < n; it++) {
        const int jt = jt0 + it;
        const int j0 = jt * 64;
        const uint32_t bo = (uint32_t)(it & 1) * ATT_BUF;
        if (it + 1 < n) {
            load_tile((jt + 1) * 64, bo ^ ATT_BUF);
            cpa_commit();
            cpa_wait1();
        } else {
            cpa_wait0();
        }
        __syncthreads();

        // ---- S = Q K^T (q pre-scaled by 1/32)
        float s_[8][4];
#pragma unroll
        for (int nt = 0; nt < 8; nt++)
#pragma unroll
            for (int i = 0; i < 4; i++) s_[nt][i] = 0.f;
        {
            const uint32_t kr = (lane & 7);
            const uint32_t kc = (lane >> 3) * 16;
#pragma unroll
            for (int kp = 0; kp < 4; kp++) {
#pragma unroll
                for (int nt = 0; nt < 8; nt++) {
                    uint32_t kh4[4], kl4[4];
                    uint32_t ro = bo + (nt * 8 + kr) * SP + kp * 64 + kc;
                    ldsm4(kh4, sb + AKH + ro);
                    ldsm4(kl4, sb + AKL + ro);
                    mma16816(s_[nt], qh[2 * kp],     kh4[0], kh4[1]);
                    mma16816(s_[nt], qh[2 * kp],     kl4[0], kl4[1]);
                    mma16816(s_[nt], ql[2 * kp],     kh4[0], kh4[1]);
                    mma16816(s_[nt], qh[2 * kp + 1], kh4[2], kh4[3]);
                    mma16816(s_[nt], qh[2 * kp + 1], kl4[2], kl4[3]);
                    mma16816(s_[nt], ql[2 * kp + 1], kh4[2], kh4[3]);
                }
            }
        }

        // ---- causal mask (tiles at/after the diagonal)
        if (jt >= 2 * qb) {
            const int rA = r0 + w * 16 + g, rB = rA + 8;
#pragma unroll
            for (int nt = 0; nt < 8; nt++) {
                const int c0 = j0 + nt * 8 + 2 * tg, c1 = c0 + 1;
                if (c0 > rA) s_[nt][0] = -CUDART_INF_F;
                if (c1 > rA) s_[nt][1] = -CUDART_INF_F;
                if (c0 > rB) s_[nt][2] = -CUDART_INF_F;
                if (c1 > rB) s_[nt][3] = -CUDART_INF_F;
            }
        }

        // ---- online softmax (registers + quad shuffles)
        float mx0 = -CUDART_INF_F, mx1 = -CUDART_INF_F;
#pragma unroll
        for (int nt = 0; nt < 8; nt++) {
            mx0 = fmaxf(mx0, fmaxf(s_[nt][0], s_[nt][1]));
            mx1 = fmaxf(mx1, fmaxf(s_[nt][2], s_[nt][3]));
        }
        mx0 = fmaxf(mx0, __shfl_xor_sync(0xffffffffu, mx0, 1));
        mx0 = fmaxf(mx0, __shfl_xor_sync(0xffffffffu, mx0, 2));
        mx1 = fmaxf(mx1, __shfl_xor_sync(0xffffffffu, mx1, 1));
        mx1 = fmaxf(mx1, __shfl_xor_sync(0xffffffffu, mx1, 2));
        const float mn0 = fmaxf(m0, mx0), mn1 = fmaxf(m1, mx1);
        const float f0 = __expf(m0 - mn0), f1 = __expf(m1 - mn1);
        m0 = mn0; m1 = mn1;
        float ps0 = 0.f, ps1 = 0.f;
#pragma unroll
        for (int nt = 0; nt < 8; nt++) {
            s_[nt][0] = __expf(s_[nt][0] - mn0);
            s_[nt][1] = __expf(s_[nt][1] - mn0);
            s_[nt][2] = __expf(s_[nt][2] - mn1);
            s_[nt][3] = __expf(s_[nt][3] - mn1);
            ps0 += s_[nt][0] + s_[nt][1];
            ps1 += s_[nt][2] + s_[nt][3];
        }
        ps0 += __shfl_xor_sync(0xffffffffu, ps0, 1);
        ps0 += __shfl_xor_sync(0xffffffffu, ps0, 2);
        ps1 += __shfl_xor_sync(0xffffffffu, ps1, 1);
        ps1 += __shfl_xor_sync(0xffffffffu, ps1, 2);
        l0 = l0 * f0 + ps0;
        l1 = l1 * f1 + ps1;
#pragma unroll
        for (int nt = 0; nt < 16; nt++) {
            o[nt][0] *= f0; o[nt][1] *= f0;
            o[nt][2] *= f1; o[nt][3] *= f1;
        }

        // ---- O += P V (P split to bf16 in registers)
#pragma unroll
        for (int ks = 0; ks < 4; ks++) {
            uint32_t pah[4], pal[4];
            split2(s_[2 * ks][0],     s_[2 * ks][1],     pah[0], pal[0]);
            split2(s_[2 * ks][2],     s_[2 * ks][3],     pah[1], pal[1]);
            split2(s_[2 * ks + 1][0], s_[2 * ks + 1][1], pah[2], pal[2]);
            split2(s_[2 * ks + 1][2], s_[2 * ks + 1][3], pah[3], pal[3]);
            const uint32_t vr = bo + (ks * 16 + (lane & 15)) * SP + (lane >> 4) * 16;
#pragma unroll
            for (int np = 0; np < 8; np++) {
                uint32_t vh4[4], vl4[4];
                ldsm4t(vh4, sb + AVH + vr + np * 32);
                ldsm4t(vl4, sb + AVL + vr + np * 32);
                float* c0 = o[2 * np];
                float* c1 = o[2 * np + 1];
                mma16816(c0, pah, vh4[0], vh4[1]);
                mma16816(c0, pah, vl4[0], vl4[1]);
                mma16816(c0, pal, vh4[0], vh4[1]);
                mma16816(c1, pah, vh4[2], vh4[3]);
                mma16816(c1, pah, vl4[2], vl4[3]);
                mma16816(c1, pal, vh4[2], vh4[3]);
            }
        }
        __syncthreads();
    }

    const int rA = w * 16 + g;
    if (ntiles <= 4) {
        // single chunk: normalize and write final output directly
        const float inv0 = 1.f / l0, inv1 = 1.f / l1;
        float* op = out + ((size_t)b * TT + r0) * HH;
#pragma unroll
        for (int nt = 0; nt < 16; nt++) {
            const int c = nt * 8 + 2 * tg;
            *(float2*)(op + (size_t)rA * HH + c) =
                make_float2(o[nt][0] * inv0, o[nt][1] * inv0);
            *(float2*)(op + (size_t)(rA + 8) * HH + c) =
                make_float2(o[nt][2] * inv1, o[nt][3] * inv1);
        }
    } else {
        const size_t pb = (size_t)((b * 16 + qb) * 8 + ch);
        float* po = g_po + pb * 128 * 128;
#pragma unroll
        for (int nt = 0; nt < 16; nt++) {
            const int c = nt * 8 + 2 * tg;
            *(float2*)(po + (size_t)rA * 128 + c)       = make_float2(o[nt][0], o[nt][1]);
            *(float2*)(po + (size_t)(rA + 8) * 128 + c) = make_float2(o[nt][2], o[nt][3]);
        }
        if (tg == 0) {
            g_pm[pb * 128 + rA] = m0;  g_pm[pb * 128 + rA + 8] = m1;
            g_pl[pb * 128 + rA] = l0;  g_pl[pb * 128 + rA + 8] = l1;
        }
    }
}

// ---------------------------------------------------------------------------
// Combine split-KV partials (qb >= 2), fully parallel:
// one thread per 4 output floats.  grid ((16-2)*16, BB) x 256 threads.
// ---------------------------------------------------------------------------
__global__ __launch_bounds__(256) void combine_kernel(float* __restrict__ out)
{
    const int qb  = 2 + (blockIdx.x >> 4);
    const int sub = blockIdx.x & 15;
    const int b   = blockIdx.y;
    const int nc  = (2 * qb + 5) >> 2;      // ceil((2qb+2)/4)

    const int e   = sub * 256 + threadIdx.x;   // 0..4095
    const int row = e >> 5;                     // 0..127
    const int c4  = (e & 31) * 4;               // 0..124

    const size_t pb = (size_t)(b * 16 + qb) * 8;

    float mv[8], M = -CUDART_INF_F;
#pragma unroll 4
    for (int c = 0; c < nc; c++) {
        mv[c] = g_pm[(pb + c) * 128 + row];
        M = fmaxf(M, mv[c]);
    }
    float wg[8], l = 0.f;
#pragma unroll 4
    for (int c = 0; c < nc; c++) {
        wg[c] = __expf(mv[c] - M);
        l += wg[c] * g_pl[(pb + c) * 128 + row];
    }
    const float inv = 1.f / l;

    float ox = 0.f, oy = 0.f, oz = 0.f, ow = 0.f;
#pragma unroll 4
    for (int c = 0; c < nc; c++) {
        const float4 p = *(const float4*)(g_po + ((pb + c) * 128 + row) * 128 + c4);
        ox += wg[c] * p.x; oy += wg[c] * p.y;
        oz += wg[c] * p.z; ow += wg[c] * p.w;
    }
    *(float4*)(out + ((size_t)b * TT + qb * 128 + row) * HH + c4) =
        make_float4(ox * inv, oy * inv, oz * inv, ow * inv);
}

// ---------------------------------------------------------------------------
extern "C" void kernel_launch(void* const* d_in, const int* in_sizes, int n_in,
                              void* d_out, int out_size)
{
    (void)in_sizes; (void)n_in; (void)out_size;
    const float* x  = (const float*)d_in[0];
    const float* Wq = (const float*)d_in[1];
    const float* Wk = (const float*)d_in[2];
    const float* Wv = (const float*)d_in[3];
    float* out = (float*)d_out;

    const int ncv = N4X + 3 * N4W;
    convert_kernel<<<(ncv + 255) / 256, 256>>>(x, Wq, Wk, Wv);

    cudaFuncSetAttribute(proj_kernel,
                         cudaFuncAttributeMaxDynamicSharedMemorySize, PROJ_SMEM);
    dim3 pgrid(BT / 64, 3);
    proj_kernel<<<pgrid, 256, PROJ_SMEM>>>();

    cudaFuncSetAttribute(attn_kernel,
                         cudaFuncAttributeMaxDynamicSharedMemorySize, ATT_SMEM);
    dim3 agrid(16, BB, 8);
    attn_kernel<<<agrid, 256, ATT_SMEM>>>(out);

    dim3 cgrid(14 * 16, BB);
    combine_kernel<<<cgrid, 256>>>(out);
}

// round 7
// speedup vs baseline: 2.9916x; 1.0492x over previous
#include <cuda_runtime.h>
#include <math_constants.h>
#include <cstdint>

#define BB 4
#define TT 2048
#define CC 1024
#define HH 128
#define BT (BB * TT)

// packed bf16-pair planes (one u32 = 2 adjacent bf16)
__device__ uint32_t g_wh[3 * CC * HH / 2], g_wl[3 * CC * HH / 2];
__device__ uint32_t g_qh[BT * HH / 2], g_ql[BT * HH / 2];
__device__ uint32_t g_kh[BT * HH / 2], g_kl[BT * HH / 2];
__device__ uint32_t g_vh[BT * HH / 2], g_vl[BT * HH / 2];
// attention partials: [B][16 qblocks][8 chunks]
__device__ float g_po[BB * 16 * 8 * 128 * HH];
__device__ float g_pm[BB * 16 * 8 * 128];
__device__ float g_pl[BB * 16 * 8 * 128];

// ---------------------------------------------------------------------------
// helpers
// ---------------------------------------------------------------------------
__device__ __forceinline__ uint32_t bf2(float lo, float hi) {
    uint32_t r;
    asm("cvt.rn.bf16x2.f32 %0, %1, %2;" : "=r"(r) : "f"(hi), "f"(lo));
    return r;
}
__device__ __forceinline__ void split2(float a, float b, uint32_t& h, uint32_t& l) {
    h = bf2(a, b);
    float ah = __uint_as_float(h << 16);
    float bh = __uint_as_float(h & 0xffff0000u);
    l = bf2(a - ah, b - bh);
}
__device__ __forceinline__ void mma16816(float c[4], const uint32_t a[4],
                                         uint32_t b0, uint32_t b1) {
    asm volatile(
        "mma.sync.aligned.m16n8k16.row.col.f32.bf16.bf16.f32 "
        "{%0,%1,%2,%3}, {%4,%5,%6,%7}, {%8,%9}, {%0,%1,%2,%3};"
        : "+f"(c[0]), "+f"(c[1]), "+f"(c[2]), "+f"(c[3])
        : "r"(a[0]), "r"(a[1]), "r"(a[2]), "r"(a[3]), "r"(b0), "r"(b1));
}
__device__ __forceinline__ void ldsm4(uint32_t* r, uint32_t addr) {
    asm volatile("ldmatrix.sync.aligned.m8n8.x4.shared.b16 {%0,%1,%2,%3}, [%4];"
                 : "=r"(r[0]), "=r"(r[1]), "=r"(r[2]), "=r"(r[3]) : "r"(addr));
}
__device__ __forceinline__ void ldsm4t(uint32_t* r, uint32_t addr) {
    asm volatile("ldmatrix.sync.aligned.m8n8.x4.trans.shared.b16 {%0,%1,%2,%3}, [%4];"
                 : "=r"(r[0]), "=r"(r[1]), "=r"(r[2]), "=r"(r[3]) : "r"(addr));
}
__device__ __forceinline__ void cpa16(uint32_t s, const void* g) {
    asm volatile("cp.async.cg.shared.global [%0], [%1], 16;" :: "r"(s), "l"(g));
}
__device__ __forceinline__ void cpa_commit() { asm volatile("cp.async.commit_group;"); }
__device__ __forceinline__ void cpa_wait0()  { asm volatile("cp.async.wait_group 0;"); }
__device__ __forceinline__ void cpa_wait1()  { asm volatile("cp.async.wait_group 1;"); }

// ---------------------------------------------------------------------------
// fp32 -> bf16 hi/lo planes for the three weight matrices only
// ---------------------------------------------------------------------------
#define N4W (CC * HH / 4)

__global__ void convert_kernel(const float* __restrict__ wq,
                               const float* __restrict__ wk,
                               const float* __restrict__ wv)
{
    int i = blockIdx.x * blockDim.x + threadIdx.x;
    if (i >= 3 * N4W) return;
    int w = i / N4W;
    int idx = i - w * N4W;
    const float* src = (w == 0) ? wq : (w == 1) ? wk : wv;
    uint32_t* dh = g_wh + w * (CC * HH / 2);
    uint32_t* dl = g_wl + w * (CC * HH / 2);
    float4 v = ((const float4*)src)[idx];
    uint32_t h0, l0, h1, l1;
    split2(v.x, v.y, h0, l0);
    split2(v.z, v.w, h1, l1);
    ((uint2*)dh)[idx] = make_uint2(h0, h1);
    ((uint2*)dl)[idx] = make_uint2(l0, l1);
}

// ---------------------------------------------------------------------------
// Projection GEMM, bf16 mma 3-term split, cp.async double-buffered,
// x converted fp32->bf16 hi/lo IN-KERNEL (no separate x convert pass).
// Block 64(M) x 128(N), BK=32.  8 warps = 4(M) x 2(N); warp tile 16x64.
// ---------------------------------------------------------------------------
#define XPB 80          // x plane pitch (bytes)
#define XFP 144         // x fp32 staging pitch (bytes), pad kills conflicts
#define WPB 272
#define PXF 0
#define SXH 9216
#define SXL 14336
#define SWH 19456
#define SWL 28160
#define PROJ_BUF 36864
#define PROJ_SMEM (2 * PROJ_BUF)

__global__ __launch_bounds__(256) void proj_kernel(const float* __restrict__ x)
{
    extern __shared__ char ps[];
    const uint32_t sb = (uint32_t)__cvta_generic_to_shared(ps);
    const int tid = threadIdx.x, lane = tid & 31, wid = tid >> 5;
    const int wm = wid & 3, wn = wid >> 2;
    const int g = lane >> 2, tg = lane & 3;
    const int m0 = blockIdx.x * 64;
    const int y = blockIdx.y;

    const uint32_t* wh = g_wh + y * (CC * HH / 2);
    const uint32_t* wl = g_wl + y * (CC * HH / 2);
    uint32_t *oh, *ol;
    if (y == 0)      { oh = g_qh; ol = g_ql; }
    else if (y == 1) { oh = g_kh; ol = g_kl; }
    else             { oh = g_vh; ol = g_vl; }

    float acc[8][4];
#pragma unroll
    for (int nt = 0; nt < 8; nt++)
#pragma unroll
        for (int i = 0; i < 4; i++) acc[nt][i] = 0.f;

    const uint32_t a_coff = (lane >> 4) * 16;
    const uint32_t b_coff = (uint32_t)(wn * 128 + (lane >> 4) * 16);

    // async loader: x fp32 tile 64x32 + W plane tiles 32x128
    auto load_k = [&](int k0, uint32_t bo) {
#pragma unroll
        for (int i = 0; i < 2; i++) {            // x fp32: 512 16B segs
            int s = tid + i * 256;
            int row = s >> 3, cs = s & 7;
            cpa16(sb + bo + PXF + row * XFP + cs * 16,
                  x + (size_t)(m0 + row) * CC + k0 + cs * 4);
        }
#pragma unroll
        for (int i = 0; i < 2; i++) {            // W planes
            int s = tid + i * 256;
            int row = s >> 4, cs = s & 15;
            size_t gi = (size_t)(k0 + row) * 64 + cs * 4;
            cpa16(sb + bo + SWH + row * WPB + cs * 16, wh + gi);
            cpa16(sb + bo + SWL + row * WPB + cs * 16, wl + gi);
        }
    };

    load_k(0, 0);
    cpa_commit();

    for (int it = 0; it < 32; it++) {
        const uint32_t bo = (uint32_t)(it & 1) * PROJ_BUF;
        if (it < 31) {
            load_k((it + 1) * 32, bo ^ PROJ_BUF);
            cpa_commit();
            cpa_wait1();
        } else {
            cpa_wait0();
        }
        __syncthreads();

        // in-place convert: x fp32 -> hi/lo planes (each thread: 1 row x 8 k)
        {
            const int row = tid >> 2, cb = (tid & 3) * 8;   // k offset
            const char* src = ps + bo + PXF + row * XFP + cb * 4;
            float4 f0 = *(const float4*)(src);
            float4 f1 = *(const float4*)(src + 16);
            uint32_t hh[4], ll[4];
            split2(f0.x, f0.y, hh[0], ll[0]);
            split2(f0.z, f0.w, hh[1], ll[1]);
            split2(f1.x, f1.y, hh[2], ll[2]);
            split2(f1.z, f1.w, hh[3], ll[3]);
            *(uint4*)(ps + bo + SXH + row * XPB + (tid & 3) * 16) =
                make_uint4(hh[0], hh[1], hh[2], hh[3]);
            *(uint4*)(ps + bo + SXL + row * XPB + (tid & 3) * 16) =
                make_uint4(ll[0], ll[1], ll[2], ll[3]);
        }
        __syncthreads();

#pragma unroll
        for (int ks = 0; ks < 2; ks++) {
            uint32_t ah[4], al[4];
            {
                uint32_t r = wm * 16 + (lane & 15);
                ldsm4(ah, sb + bo + SXH + r * XPB + ks * 32 + a_coff);
                ldsm4(al, sb + bo + SXL + r * XPB + ks * 32 + a_coff);
            }
#pragma unroll
            for (int np = 0; np < 4; np++) {
                uint32_t bh[4], bl[4];
                uint32_t r = ks * 16 + (lane & 15);
                ldsm4t(bh, sb + bo + SWH + r * WPB + b_coff + np * 32);
                ldsm4t(bl, sb + bo + SWL + r * WPB + b_coff + np * 32);
#pragma unroll
                for (int h2 = 0; h2 < 2; h2++) {
                    float* c = acc[np * 2 + h2];
                    mma16816(c, ah, bh[2 * h2], bh[2 * h2 + 1]);
                    mma16816(c, ah, bl[2 * h2], bl[2 * h2 + 1]);
                    mma16816(c, al, bh[2 * h2], bh[2 * h2 + 1]);
                }
            }
        }
        __syncthreads();
    }

    // q pre-scaled by C^-0.5 * log2(e)  (attention exps run in base-2)
    const float sc = (y == 0) ? 0.03125f * 1.44269504f : 1.0f;
    const int r1 = m0 + wm * 16 + g;
#pragma unroll
    for (int nt = 0; nt < 8; nt++) {
        const int c = wn * 64 + nt * 8 + 2 * tg;
        uint32_t h, l;
        split2(acc[nt][0] * sc, acc[nt][1] * sc, h, l);
        oh[(size_t)r1 * 64 + (c >> 1)] = h;
        ol[(size_t)r1 * 64 + (c >> 1)] = l;
        split2(acc[nt][2] * sc, acc[nt][3] * sc, h, l);
        oh[(size_t)(r1 + 8) * 64 + (c >> 1)] = h;
        ol[(size_t)(r1 + 8) * 64 + (c >> 1)] = l;
    }
}

// ---------------------------------------------------------------------------
// Flash attention, bf16 mma 3-term split, cp.async double-buffered K/V.
// Block = 128 query rows x chunk of <=4 key tiles (64 keys each).
// Softmax in base-2 (q carries log2(e)).
// ---------------------------------------------------------------------------
#define SP 272
#define AKH 0
#define AKL 17408
#define AVH 34816
#define AVL 52224
#define ATT_BUF 69632
#define ATT_SMEM (2 * ATT_BUF)

__global__ __launch_bounds__(256) void attn_kernel(float* __restrict__ out)
{
    const int qb = blockIdx.x;                 // 0..15
    const int b  = blockIdx.y;                 // 0..3
    const int ch = blockIdx.z;                 // 0..7
    const int ntiles = 2 * qb + 2;
    if (ch * 4 >= ntiles) return;

    extern __shared__ char as_[];
    const uint32_t sb = (uint32_t)__cvta_generic_to_shared(as_);
    const int tid = threadIdx.x, lane = tid & 31, w = tid >> 5;
    const int g = lane >> 2, tg = lane & 3;
    const int r0 = qb * 128;

    // ---- stage Q into buffer0 (hi at 0, lo at AVH), async then to registers
    {
        const uint32_t* sh = g_qh + (size_t)b * TT * 64;
        const uint32_t* sl = g_ql + (size_t)b * TT * 64;
#pragma unroll
        for (int i = 0; i < 8; i++) {
            int s = tid + i * 256;
            int row = s >> 4, cs = s & 15;
            size_t gi = (size_t)(r0 + row) * 64 + cs * 4;
            cpa16(sb + row * SP + cs * 16, sh + gi);
            cpa16(sb + AVH + row * SP + cs * 16, sl + gi);
        }
        cpa_commit();
        cpa_wait0();
    }
    __syncthreads();
    uint32_t qh[8][4], ql[8][4];
    {
        const uint32_t br = w * 16 + (lane & 15);
        const uint32_t co = (lane >> 4) * 16;
#pragma unroll
        for (int ks = 0; ks < 8; ks++) {
            ldsm4(qh[ks], sb + br * SP + ks * 32 + co);
            ldsm4(ql[ks], sb + AVH + br * SP + ks * 32 + co);
        }
    }
    __syncthreads();   // Q in registers; buffer0 reusable

    float o[16][4];
#pragma unroll
    for (int nt = 0; nt < 16; nt++)
#pragma unroll
        for (int i = 0; i < 4; i++) o[nt][i] = 0.f;
    float m0 = -CUDART_INF_F, m1 = -CUDART_INF_F, l0 = 0.f, l1 = 0.f;

    const uint32_t* khp = g_kh + (size_t)b * TT * 64;
    const uint32_t* klp = g_kl + (size_t)b * TT * 64;
    const uint32_t* vhp = g_vh + (size_t)b * TT * 64;
    const uint32_t* vlp = g_vl + (size_t)b * TT * 64;

    auto load_tile = [&](int j0, uint32_t bo) {
#pragma unroll
        for (int i = 0; i < 4; i++) {
            int s = tid + i * 256;
            int row = s >> 4, cs = s & 15;
            size_t gi = (size_t)(j0 + row) * 64 + cs * 4;
            uint32_t so = bo + row * SP + cs * 16;
            cpa16(sb + so + AKH, khp + gi);
            cpa16(sb + so + AKL, klp + gi);
            cpa16(sb + so + AVH, vhp + gi);
            cpa16(sb + so + AVL, vlp + gi);
        }
    };

    const int jt0 = ch * 4;
    const int n = min(jt0 + 4, ntiles) - jt0;

    load_tile(jt0 * 64, 0);
    cpa_commit();

    for (int it = 0; it < n; it++) {
        const int jt = jt0 + it;
        const int j0 = jt * 64;
        const uint32_t bo = (uint32_t)(it & 1) * ATT_BUF;
        if (it + 1 < n) {
            load_tile((jt + 1) * 64, bo ^ ATT_BUF);
            cpa_commit();
            cpa_wait1();
        } else {
            cpa_wait0();
        }
        __syncthreads();

        // ---- S = Q K^T  (q pre-scaled by 1/32*log2e)
        float s_[8][4];
#pragma unroll
        for (int nt = 0; nt < 8; nt++)
#pragma unroll
            for (int i = 0; i < 4; i++) s_[nt][i] = 0.f;
        {
            const uint32_t kr = (lane & 7);
            const uint32_t kc = (lane >> 3) * 16;
#pragma unroll
            for (int kp = 0; kp < 4; kp++) {
#pragma unroll
                for (int nt = 0; nt < 8; nt++) {
                    uint32_t kh4[4], kl4[4];
                    uint32_t ro = bo + (nt * 8 + kr) * SP + kp * 64 + kc;
                    ldsm4(kh4, sb + AKH + ro);
                    ldsm4(kl4, sb + AKL + ro);
                    mma16816(s_[nt], qh[2 * kp],     kh4[0], kh4[1]);
                    mma16816(s_[nt], qh[2 * kp],     kl4[0], kl4[1]);
                    mma16816(s_[nt], ql[2 * kp],     kh4[0], kh4[1]);
                    mma16816(s_[nt], qh[2 * kp + 1], kh4[2], kh4[3]);
                    mma16816(s_[nt], qh[2 * kp + 1], kl4[2], kl4[3]);
                    mma16816(s_[nt], ql[2 * kp + 1], kh4[2], kh4[3]);
                }
            }
        }

        // ---- causal mask (tiles at/after the diagonal)
        if (jt >= 2 * qb) {
            const int rA = r0 + w * 16 + g, rB = rA + 8;
#pragma unroll
            for (int nt = 0; nt < 8; nt++) {
                const int c0 = j0 + nt * 8 + 2 * tg, c1 = c0 + 1;
                if (c0 > rA) s_[nt][0] = -CUDART_INF_F;
                if (c1 > rA) s_[nt][1] = -CUDART_INF_F;
                if (c0 > rB) s_[nt][2] = -CUDART_INF_F;
                if (c1 > rB) s_[nt][3] = -CUDART_INF_F;
            }
        }

        // ---- online softmax, base-2 (registers + quad shuffles)
        float mx0 = -CUDART_INF_F, mx1 = -CUDART_INF_F;
#pragma unroll
        for (int nt = 0; nt < 8; nt++) {
            mx0 = fmaxf(mx0, fmaxf(s_[nt][0], s_[nt][1]));
            mx1 = fmaxf(mx1, fmaxf(s_[nt][2], s_[nt][3]));
        }
        mx0 = fmaxf(mx0, __shfl_xor_sync(0xffffffffu, mx0, 1));
        mx0 = fmaxf(mx0, __shfl_xor_sync(0xffffffffu, mx0, 2));
        mx1 = fmaxf(mx1, __shfl_xor_sync(0xffffffffu, mx1, 1));
        mx1 = fmaxf(mx1, __shfl_xor_sync(0xffffffffu, mx1, 2));
        const float mn0 = fmaxf(m0, mx0), mn1 = fmaxf(m1, mx1);
        const float f0 = exp2f(m0 - mn0), f1 = exp2f(m1 - mn1);
        m0 = mn0; m1 = mn1;
        float ps0 = 0.f, ps1 = 0.f;
#pragma unroll
        for (int nt = 0; nt < 8; nt++) {
            s_[nt][0] = exp2f(s_[nt][0] - mn0);
            s_[nt][1] = exp2f(s_[nt][1] - mn0);
            s_[nt][2] = exp2f(s_[nt][2] - mn1);
            s_[nt][3] = exp2f(s_[nt][3] - mn1);
            ps0 += s_[nt][0] + s_[nt][1];
            ps1 += s_[nt][2] + s_[nt][3];
        }
        ps0 += __shfl_xor_sync(0xffffffffu, ps0, 1);
        ps0 += __shfl_xor_sync(0xffffffffu, ps0, 2);
        ps1 += __shfl_xor_sync(0xffffffffu, ps1, 1);
        ps1 += __shfl_xor_sync(0xffffffffu, ps1, 2);
        l0 = l0 * f0 + ps0;
        l1 = l1 * f1 + ps1;
#pragma unroll
        for (int nt = 0; nt < 16; nt++) {
            o[nt][0] *= f0; o[nt][1] *= f0;
            o[nt][2] *= f1; o[nt][3] *= f1;
        }

        // ---- O += P V (P split to bf16 in registers)
#pragma unroll
        for (int ks = 0; ks < 4; ks++) {
            uint32_t pah[4], pal[4];
            split2(s_[2 * ks][0],     s_[2 * ks][1],     pah[0], pal[0]);
            split2(s_[2 * ks][2],     s_[2 * ks][3],     pah[1], pal[1]);
            split2(s_[2 * ks + 1][0], s_[2 * ks + 1][1], pah[2], pal[2]);
            split2(s_[2 * ks + 1][2], s_[2 * ks + 1][3], pah[3], pal[3]);
            const uint32_t vr = bo + (ks * 16 + (lane & 15)) * SP + (lane >> 4) * 16;
#pragma unroll
            for (int np = 0; np < 8; np++) {
                uint32_t vh4[4], vl4[4];
                ldsm4t(vh4, sb + AVH + vr + np * 32);
                ldsm4t(vl4, sb + AVL + vr + np * 32);
                float* c0 = o[2 * np];
                float* c1 = o[2 * np + 1];
                mma16816(c0, pah, vh4[0], vh4[1]);
                mma16816(c0, pah, vl4[0], vl4[1]);
                mma16816(c0, pal, vh4[0], vh4[1]);
                mma16816(c1, pah, vh4[2], vh4[3]);
                mma16816(c1, pah, vl4[2], vl4[3]);
                mma16816(c1, pal, vh4[2], vh4[3]);
            }
        }
        __syncthreads();
    }

    const int rA = w * 16 + g;
    if (ntiles <= 4) {
        // single chunk: normalize and write final output directly
        const float inv0 = 1.f / l0, inv1 = 1.f / l1;
        float* op = out + ((size_t)b * TT + r0) * HH;
#pragma unroll
        for (int nt = 0; nt < 16; nt++) {
            const int c = nt * 8 + 2 * tg;
            *(float2*)(op + (size_t)rA * HH + c) =
                make_float2(o[nt][0] * inv0, o[nt][1] * inv0);
            *(float2*)(op + (size_t)(rA + 8) * HH + c) =
                make_float2(o[nt][2] * inv1, o[nt][3] * inv1);
        }
    } else {
        const size_t pb = (size_t)((b * 16 + qb) * 8 + ch);
        float* po = g_po + pb * 128 * 128;
#pragma unroll
        for (int nt = 0; nt < 16; nt++) {
            const int c = nt * 8 + 2 * tg;
            *(float2*)(po + (size_t)rA * 128 + c)       = make_float2(o[nt][0], o[nt][1]);
            *(float2*)(po + (size_t)(rA + 8) * 128 + c) = make_float2(o[nt][2], o[nt][3]);
        }
        if (tg == 0) {
            g_pm[pb * 128 + rA] = m0;  g_pm[pb * 128 + rA + 8] = m1;
            g_pl[pb * 128 + rA] = l0;  g_pl[pb * 128 + rA + 8] = l1;
        }
    }
}

// ---------------------------------------------------------------------------
// Combine split-KV partials (qb >= 2): one thread per 8 output floats.
// grid ((16-2)*8, BB) x 256 threads.
// ---------------------------------------------------------------------------
__global__ __launch_bounds__(256) void combine_kernel(float* __restrict__ out)
{
    const int qb  = 2 + (blockIdx.x >> 3);
    const int sub = blockIdx.x & 7;
    const int b   = blockIdx.y;
    const int nc  = (2 * qb + 5) >> 2;      // ceil((2qb+2)/4)

    const int e   = sub * 256 + threadIdx.x;   // 0..2047
    const int row = e >> 4;                     // 0..127
    const int c8  = (e & 15) * 8;               // 0..120

    const size_t pb = (size_t)(b * 16 + qb) * 8;

    float mv[8], M = -CUDART_INF_F;
#pragma unroll 4
    for (int c = 0; c < nc; c++) {
        mv[c] = __ldg(&g_pm[(pb + c) * 128 + row]);
        M = fmaxf(M, mv[c]);
    }
    float wg[8], l = 0.f;
#pragma unroll 4
    for (int c = 0; c < nc; c++) {
        wg[c] = exp2f(mv[c] - M);
        l += wg[c] * __ldg(&g_pl[(pb + c) * 128 + row]);
    }
    const float inv = 1.f / l;

    float a0 = 0.f, a1 = 0.f, a2 = 0.f, a3 = 0.f;
    float b0 = 0.f, b1 = 0.f, b2 = 0.f, b3 = 0.f;
#pragma unroll 4
    for (int c = 0; c < nc; c++) {
        const float4* base = (const float4*)(g_po + ((pb + c) * 128 + row) * 128 + c8);
        const float4 p = __ldg(base);
        const float4 q = __ldg(base + 1);
        a0 += wg[c] * p.x; a1 += wg[c] * p.y; a2 += wg[c] * p.z; a3 += wg[c] * p.w;
        b0 += wg[c] * q.x; b1 += wg[c] * q.y; b2 += wg[c] * q.z; b3 += wg[c] * q.w;
    }
    float* op = out + ((size_t)b * TT + qb * 128 + row) * HH + c8;
    *(float4*)(op)     = make_float4(a0 * inv, a1 * inv, a2 * inv, a3 * inv);
    *(float4*)(op + 4) = make_float4(b0 * inv, b1 * inv, b2 * inv, b3 * inv);
}

// ---------------------------------------------------------------------------
extern "C" void kernel_launch(void* const* d_in, const int* in_sizes, int n_in,
                              void* d_out, int out_size)
{
    (void)in_sizes; (void)n_in; (void)out_size;
    const float* x  = (const float*)d_in[0];
    const float* Wq = (const float*)d_in[1];
    const float* Wk = (const float*)d_in[2];
    const float* Wv = (const float*)d_in[3];
    float* out = (float*)d_out;

    convert_kernel<<<(3 * N4W + 255) / 256, 256>>>(Wq, Wk, Wv);

    cudaFuncSetAttribute(proj_kernel,
                         cudaFuncAttributeMaxDynamicSharedMemorySize, PROJ_SMEM);
    dim3 pgrid(BT / 64, 3);
    proj_kernel<<<pgrid, 256, PROJ_SMEM>>>(x);

    cudaFuncSetAttribute(attn_kernel,
                         cudaFuncAttributeMaxDynamicSharedMemorySize, ATT_SMEM);
    dim3 agrid(16, BB, 8);
    attn_kernel<<<agrid, 256, ATT_SMEM>>>(out);

    dim3 cgrid(14 * 8, BB);
    combine_kernel<<<cgrid, 256>>>(out);
}